// round 1
// baseline (speedup 1.0000x reference)
#include <cuda_runtime.h>

#define DIMC 768
#define NH 12
#define HD 64
#define BB 16
#define NN 640
#define MROWS (BB * NN)      /* 10240 */
#define QKVN (3 * DIMC)      /* 2304 */
#define SCALE_F 0.125f

/* scratch (allocation-free rule: __device__ globals) */
__device__ float g_q[(size_t)BB * NH * NN * HD];
__device__ float g_k[(size_t)BB * NH * NN * HD];
__device__ float g_v[(size_t)BB * NH * NN * HD];
__device__ float g_att[(size_t)MROWS * DIMC];

/* ------------------------------------------------------------------ */
/* 128x128x16 SGEMM, 256 threads, 8x8 per thread.                      */
/* EPI==0: C = A*B + bias scattered into g_q/g_k/g_v ([B,H,N,D])       */
/* EPI==1: A := g_att, C = A*B + bias written dense to C               */
/* ------------------------------------------------------------------ */
template <int EPI>
__global__ void __launch_bounds__(256) sgemm128(
    const float* __restrict__ A, const float* __restrict__ Bm,
    const float* __restrict__ bias, float* __restrict__ C,
    int M, int N, int K)
{
    __shared__ float As[16][132];
    __shared__ float Bs[16][128];

    const float* Ap = (EPI == 1) ? (const float*)g_att : A;

    const int tid = threadIdx.x;
    const int m0 = blockIdx.y * 128;
    const int n0 = blockIdx.x * 128;
    const int tx = tid & 15, ty = tid >> 4;

    float acc[8][8];
#pragma unroll
    for (int i = 0; i < 8; i++)
#pragma unroll
        for (int j = 0; j < 8; j++) acc[i][j] = 0.f;

    const int ar = tid >> 2, ac = (tid & 3) * 4;
    const int br = tid >> 5, bc = (tid & 31) * 4;

    for (int k0 = 0; k0 < K; k0 += 16) {
#pragma unroll
        for (int i = 0; i < 2; i++) {
            int row = ar + i * 64;
            float4 va = *(const float4*)&Ap[(size_t)(m0 + row) * K + k0 + ac];
            As[ac + 0][row] = va.x;
            As[ac + 1][row] = va.y;
            As[ac + 2][row] = va.z;
            As[ac + 3][row] = va.w;
        }
#pragma unroll
        for (int i = 0; i < 2; i++) {
            int row = br + i * 8;
            float4 vb = *(const float4*)&Bm[(size_t)(k0 + row) * N + n0 + bc];
            *(float4*)&Bs[row][bc] = vb;
        }
        __syncthreads();
#pragma unroll
        for (int kk = 0; kk < 16; kk++) {
            float a[8], b[8];
            *(float4*)&a[0] = *(const float4*)&As[kk][ty * 8];
            *(float4*)&a[4] = *(const float4*)&As[kk][ty * 8 + 4];
            *(float4*)&b[0] = *(const float4*)&Bs[kk][tx * 8];
            *(float4*)&b[4] = *(const float4*)&Bs[kk][tx * 8 + 4];
#pragma unroll
            for (int i = 0; i < 8; i++)
#pragma unroll
                for (int j = 0; j < 8; j++)
                    acc[i][j] = fmaf(a[i], b[j], acc[i][j]);
        }
        __syncthreads();
    }

#pragma unroll
    for (int i = 0; i < 8; i++) {
        int m = m0 + ty * 8 + i;
        if (EPI == 0) {
            int bi = m / NN, n = m % NN;
#pragma unroll
            for (int j = 0; j < 8; j++) {
                int c = n0 + tx * 8 + j;
                float val = acc[i][j] + bias[c];
                int which = c / DIMC;
                int rem = c % DIMC;
                int h = rem / HD, d = rem % HD;
                size_t dst = (((size_t)(bi * NH + h)) * NN + n) * HD + d;
                float* buf = (which == 0) ? g_q : (which == 1) ? g_k : g_v;
                buf[dst] = val;
            }
        } else {
            int c0 = n0 + tx * 8;
            float4 o0, o1;
            o0.x = acc[i][0] + bias[c0 + 0];
            o0.y = acc[i][1] + bias[c0 + 1];
            o0.z = acc[i][2] + bias[c0 + 2];
            o0.w = acc[i][3] + bias[c0 + 3];
            o1.x = acc[i][4] + bias[c0 + 4];
            o1.y = acc[i][5] + bias[c0 + 5];
            o1.z = acc[i][6] + bias[c0 + 6];
            o1.w = acc[i][7] + bias[c0 + 7];
            *(float4*)&C[(size_t)m * N + c0] = o0;
            *(float4*)&C[(size_t)m * N + c0 + 4] = o1;
        }
    }
}

/* ------------------------------------------------------------------ */
/* Fused attention: per block = (64 query rows, head h, batch b).      */
/* Streams 64-key tiles: s = qk^T*scale; keeps two accumulators:       */
/*   accS += exp(s) * v   (softmax branch, normalized by row-sum l)    */
/*   accR += relu(s)^2 * v                                             */
/* No max-subtraction: s ~ N(0,1), exp safe in fp32.                   */
/* ------------------------------------------------------------------ */
__global__ void __launch_bounds__(256) attn_kernel(const float* __restrict__ wblend)
{
    extern __shared__ float sm[];
    float* sQ = sm;             /* 64 x 65 */
    float* sK = sQ + 64 * 65;   /* 64 x 65 */
    float* sV = sK + 64 * 65;   /* 64 x 68 */
    float* sE = sV + 64 * 68;   /* 64 x 68 */
    float* sR = sE + 64 * 68;   /* 64 x 68 */
    float* sL = sR + 64 * 68;   /* 64      */

    const int tid = threadIdx.x;
    const int nt = blockIdx.x, h = blockIdx.y, bz = blockIdx.z;
    const size_t base = ((size_t)bz * NH + h) * NN * HD;
    const float* qg = g_q + base + (size_t)nt * 64 * HD;
    const float* kg = g_k + base;
    const float* vg = g_v + base;

    /* load Q tile */
#pragma unroll
    for (int i = 0; i < 4; i++) {
        int idx = tid + i * 256;
        int r = idx >> 4, c = (idx & 15) << 2;
        float4 v = *(const float4*)(qg + (size_t)r * HD + c);
        sQ[r * 65 + c + 0] = v.x;
        sQ[r * 65 + c + 1] = v.y;
        sQ[r * 65 + c + 2] = v.z;
        sQ[r * 65 + c + 3] = v.w;
    }
    if (tid < 64) sL[tid] = 0.f;

    float accS[16], accR[16];
#pragma unroll
    for (int i = 0; i < 16; i++) { accS[i] = 0.f; accR[i] = 0.f; }

    const int vr = tid >> 2, dc = tid & 3;   /* @v phase: row, d-chunk */
    const int rg = tid >> 4, jg = tid & 15;  /* s phase: 4x4 tile coords */

    __syncthreads();

    for (int kt = 0; kt < NN / 64; kt++) {
        /* load K,V tiles */
#pragma unroll
        for (int i = 0; i < 4; i++) {
            int idx = tid + i * 256;
            int r = idx >> 4, c = (idx & 15) << 2;
            float4 vk = *(const float4*)(kg + (size_t)(kt * 64 + r) * HD + c);
            sK[r * 65 + c + 0] = vk.x;
            sK[r * 65 + c + 1] = vk.y;
            sK[r * 65 + c + 2] = vk.z;
            sK[r * 65 + c + 3] = vk.w;
            float4 vv = *(const float4*)(vg + (size_t)(kt * 64 + r) * HD + c);
            sV[r * 68 + c + 0] = vv.x;
            sV[r * 68 + c + 1] = vv.y;
            sV[r * 68 + c + 2] = vv.z;
            sV[r * 68 + c + 3] = vv.w;
        }
        __syncthreads();

        /* s = q k^T (4x4 register tile per thread) */
        float s[4][4];
#pragma unroll
        for (int i = 0; i < 4; i++)
#pragma unroll
            for (int j = 0; j < 4; j++) s[i][j] = 0.f;

#pragma unroll 8
        for (int d = 0; d < HD; d++) {
            float qv[4], kv[4];
#pragma unroll
            for (int i = 0; i < 4; i++) qv[i] = sQ[(rg * 4 + i) * 65 + d];
#pragma unroll
            for (int j = 0; j < 4; j++) kv[j] = sK[(jg * 4 + j) * 65 + d];
#pragma unroll
            for (int i = 0; i < 4; i++)
#pragma unroll
                for (int j = 0; j < 4; j++)
                    s[i][j] = fmaf(qv[i], kv[j], s[i][j]);
        }

        float esum[4];
#pragma unroll
        for (int i = 0; i < 4; i++) {
            esum[i] = 0.f;
#pragma unroll
            for (int j = 0; j < 4; j++) {
                float sv = s[i][j] * SCALE_F;
                float e = __expf(sv);
                float rl = (sv > 0.f) ? sv * sv : 0.f;
                sE[(rg * 4 + i) * 68 + jg * 4 + j] = e;
                sR[(rg * 4 + i) * 68 + jg * 4 + j] = rl;
                esum[i] += e;
            }
        }
        /* row-sum reduce over the 16 jg lanes (stays within half-warp) */
#pragma unroll
        for (int off = 1; off < 16; off <<= 1)
#pragma unroll
            for (int i = 0; i < 4; i++)
                esum[i] += __shfl_xor_sync(0xffffffffu, esum[i], off);
        if (jg == 0) {
#pragma unroll
            for (int i = 0; i < 4; i++) sL[rg * 4 + i] += esum[i];
        }
        __syncthreads();

        /* accumulate both branches against V */
#pragma unroll 4
        for (int j = 0; j < 64; j++) {
            float e = sE[vr * 68 + j];
            float rl = sR[vr * 68 + j];
#pragma unroll
            for (int q = 0; q < 4; q++) {
                float4 vv = *(const float4*)(sV + j * 68 + dc * 16 + q * 4);
                accS[q * 4 + 0] = fmaf(e, vv.x, accS[q * 4 + 0]);
                accS[q * 4 + 1] = fmaf(e, vv.y, accS[q * 4 + 1]);
                accS[q * 4 + 2] = fmaf(e, vv.z, accS[q * 4 + 2]);
                accS[q * 4 + 3] = fmaf(e, vv.w, accS[q * 4 + 3]);
                accR[q * 4 + 0] = fmaf(rl, vv.x, accR[q * 4 + 0]);
                accR[q * 4 + 1] = fmaf(rl, vv.y, accR[q * 4 + 1]);
                accR[q * 4 + 2] = fmaf(rl, vv.z, accR[q * 4 + 2]);
                accR[q * 4 + 3] = fmaf(rl, vv.w, accR[q * 4 + 3]);
            }
        }
        __syncthreads();
    }

    /* blend weights: ws = softmax(w) */
    float w0 = wblend[0], w1 = wblend[1];
    float ws0 = 1.f / (1.f + __expf(w1 - w0));
    float ws1 = 1.f - ws0;
    float inv = ws0 / sL[vr];

    float* outp = g_att + ((size_t)(bz * NN) + nt * 64 + vr) * DIMC + h * HD + dc * 16;
#pragma unroll
    for (int q = 0; q < 4; q++) {
        float4 o;
        o.x = accS[q * 4 + 0] * inv + accR[q * 4 + 0] * ws1;
        o.y = accS[q * 4 + 1] * inv + accR[q * 4 + 1] * ws1;
        o.z = accS[q * 4 + 2] * inv + accR[q * 4 + 2] * ws1;
        o.w = accS[q * 4 + 3] * inv + accR[q * 4 + 3] * ws1;
        *(float4*)(outp + q * 4) = o;
    }
}

/* ------------------------------------------------------------------ */
extern "C" void kernel_launch(void* const* d_in, const int* in_sizes, int n_in,
                              void* d_out, int out_size)
{
    (void)in_sizes; (void)n_in; (void)out_size;
    const float* x      = (const float*)d_in[0];
    const float* qkv_w  = (const float*)d_in[1];
    const float* qkv_b  = (const float*)d_in[2];
    const float* proj_w = (const float*)d_in[3];
    const float* proj_b = (const float*)d_in[4];
    const float* w      = (const float*)d_in[5];
    float* out = (float*)d_out;

    const int attn_smem = (64 * 65 * 2 + 64 * 68 * 3 + 64) * 4; /* 85760 B */
    cudaFuncSetAttribute(attn_kernel,
                         cudaFuncAttributeMaxDynamicSharedMemorySize, attn_smem);

    dim3 g1(QKVN / 128, MROWS / 128);   /* 18 x 80 */
    sgemm128<0><<<g1, 256>>>(x, qkv_w, qkv_b, nullptr, MROWS, QKVN, DIMC);

    dim3 ga(NN / 64, NH, BB);           /* 10 x 12 x 16 */
    attn_kernel<<<ga, 256, attn_smem>>>(w);

    dim3 g2(DIMC / 128, MROWS / 128);   /* 6 x 80 */
    sgemm128<1><<<g2, 256>>>(nullptr, proj_w, proj_b, out, MROWS, DIMC, DIMC);
}

// round 3
// speedup vs baseline: 1.4207x; 1.4207x over previous
#include <cuda_runtime.h>
#include <stdint.h>

#define DIMC 768
#define NH 12
#define HD 64
#define BB 16
#define NN 640
#define MROWS (BB * NN)      /* 10240 */
#define QKVN (3 * DIMC)      /* 2304 */
#define SCALE_F 0.125f

/* GEMM tiling */
#define BM 128
#define BN 128
#define BK 32
#define SB_STRIDE 36                       /* B smem row stride (floats) */
#define SA_BYTES (BM * BK * 4)             /* 16384 */
#define SB_BYTES (BN * SB_STRIDE * 4)      /* 18432 */
#define STAGE_BYTES (SA_BYTES + SB_BYTES)  /* 34816 */
#define GSM_TOTAL (2 * STAGE_BYTES)        /* 69632 */

/* scratch (allocation-free rule: __device__ globals) */
__device__ float g_q[(size_t)BB * NH * NN * HD];
__device__ float g_k[(size_t)BB * NH * NN * HD];
__device__ float g_v[(size_t)BB * NH * NN * HD];
__device__ float g_att[(size_t)MROWS * DIMC];
__device__ float g_wt1[(size_t)QKVN * DIMC];   /* qkv_w^T  [2304,768] */
__device__ float g_wt2[(size_t)DIMC * DIMC];   /* proj_w^T [768,768]  */

/* ---------------- helpers ---------------- */
__device__ __forceinline__ uint32_t smem_u32(const void* p) {
    uint32_t a;
    asm("{ .reg .u64 t; cvta.to.shared.u64 t, %1; cvt.u32.u64 %0, t; }"
        : "=r"(a) : "l"(p));
    return a;
}

__device__ __forceinline__ float to_tf32(float x) {
    float r;
    asm("cvt.rna.tf32.f32 %0, %1;" : "=f"(r) : "f"(x));
    return r;
}

#define LDMATRIX_X4(r0, r1, r2, r3, addr) \
    asm volatile("ldmatrix.sync.aligned.m8n8.x4.shared.b16 {%0,%1,%2,%3}, [%4];" \
        : "=r"(r0), "=r"(r1), "=r"(r2), "=r"(r3) : "r"(addr))

#define MMA_TF32(C, A, B) \
    asm volatile("mma.sync.aligned.m16n8k8.row.col.f32.tf32.tf32.f32 " \
        "{%0,%1,%2,%3}, {%4,%5,%6,%7}, {%8,%9}, {%0,%1,%2,%3};" \
        : "+f"((C)[0]), "+f"((C)[1]), "+f"((C)[2]), "+f"((C)[3]) \
        : "r"((A)[0]), "r"((A)[1]), "r"((A)[2]), "r"((A)[3]), \
          "r"((B)[0]), "r"((B)[1]))

/* ------------------------------------------------------------------ */
/* tf32 mma.sync GEMM: C[M,N] = A[M,K] @ Bt[N,K]^T + bias              */
/* 256 thr = 8 warps (2m x 4n), warp tile 64x32, block 128x128, K=32   */
/* EPI==0: A = x, Bt = g_wt1, scatter into g_q/g_k/g_v                 */
/* EPI==1: A = g_att, Bt = g_wt2, dense out                            */
/* ------------------------------------------------------------------ */
template <int EPI>
__global__ void __launch_bounds__(256)
tgemm(const float* __restrict__ Ain, const float* __restrict__ bias,
      float* __restrict__ Cout, int N, int K)
{
    extern __shared__ char smraw[];
    const float* Ap = (EPI == 0) ? Ain : (const float*)g_att;
    const float* Bt = (EPI == 0) ? (const float*)g_wt1 : (const float*)g_wt2;

    const int tid = threadIdx.x;
    const int m0 = blockIdx.y * BM, n0 = blockIdx.x * BN;
    const int lane = tid & 31, wid = tid >> 5;
    const int wm = (wid >> 2) * 64;
    const int wn = (wid & 3) * 32;
    const int g = lane >> 2, tg = lane & 3;
    const int lr = lane & 15, half = lane >> 4;   /* ldmatrix lane mapping */

    const int arow = tid >> 3, ac4 = tid & 7;     /* global/staging indices */

    float c[4][4][4];
#pragma unroll
    for (int mf = 0; mf < 4; mf++)
#pragma unroll
        for (int nf = 0; nf < 4; nf++)
#pragma unroll
            for (int r = 0; r < 4; r++) c[mf][nf][r] = 0.f;

    float4 ra[4], rb[4];
    const uint32_t sbase = smem_u32(smraw);

#define LDG_TILE(kt) do {                                                      \
    const float* Ag = Ap + (size_t)m0 * K + (kt) * BK;                         \
    const float* Bg = Bt + (size_t)n0 * K + (kt) * BK;                         \
    _Pragma("unroll")                                                          \
    for (int i = 0; i < 4; i++)                                                \
        ra[i] = *(const float4*)(Ag + (size_t)(arow + i * 32) * K + ac4 * 4);  \
    _Pragma("unroll")                                                          \
    for (int i = 0; i < 4; i++)                                                \
        rb[i] = *(const float4*)(Bg + (size_t)(arow + i * 32) * K + ac4 * 4);  \
} while (0)

#define STS_TILE(st) do {                                                      \
    char* base = smraw + (st) * STAGE_BYTES;                                   \
    _Pragma("unroll")                                                          \
    for (int i = 0; i < 4; i++) {                                              \
        int r = arow + i * 32;                                                 \
        float4 v = ra[i];                                                      \
        v.x = to_tf32(v.x); v.y = to_tf32(v.y);                                \
        v.z = to_tf32(v.z); v.w = to_tf32(v.w);                                \
        *(float4*)(base + r * 128 + ((ac4 ^ (r & 7)) * 16)) = v;               \
    }                                                                          \
    float* bb = (float*)(base + SA_BYTES);                                     \
    _Pragma("unroll")                                                          \
    for (int i = 0; i < 4; i++) {                                              \
        int r = arow + i * 32;                                                 \
        float4 v = rb[i];                                                      \
        v.x = to_tf32(v.x); v.y = to_tf32(v.y);                                \
        v.z = to_tf32(v.z); v.w = to_tf32(v.w);                                \
        *(float4*)(bb + r * SB_STRIDE + ac4 * 4) = v;                          \
    }                                                                          \
} while (0)

#define COMPUTE(st) do {                                                       \
    const uint32_t a_s = sbase + (st) * STAGE_BYTES;                           \
    const float* bsm = (const float*)(smraw + (st) * STAGE_BYTES + SA_BYTES);  \
    _Pragma("unroll")                                                          \
    for (int ks = 0; ks < 4; ks++) {                                           \
        uint32_t a[4][4];                                                      \
        _Pragma("unroll")                                                      \
        for (int mf = 0; mf < 4; mf++) {                                       \
            int r = wm + mf * 16 + lr;                                         \
            int chunk = (2 * ks + half) ^ (r & 7);                             \
            uint32_t addr = a_s + r * 128 + chunk * 16;                        \
            LDMATRIX_X4(a[mf][0], a[mf][1], a[mf][2], a[mf][3], addr);         \
        }                                                                      \
        uint32_t b[4][2];                                                      \
        _Pragma("unroll")                                                      \
        for (int nf = 0; nf < 4; nf++) {                                       \
            const uint32_t* bp = (const uint32_t*)(bsm                         \
                + (wn + nf * 8 + g) * SB_STRIDE + ks * 8 + tg);                \
            b[nf][0] = bp[0];                                                  \
            b[nf][1] = bp[4];                                                  \
        }                                                                      \
        _Pragma("unroll")                                                      \
        for (int mf = 0; mf < 4; mf++)                                         \
            _Pragma("unroll")                                                  \
            for (int nf = 0; nf < 4; nf++)                                     \
                MMA_TF32(c[mf][nf], a[mf], b[nf]);                             \
    }                                                                          \
} while (0)

    const int nkt = K / BK;
    LDG_TILE(0);
    STS_TILE(0);
    __syncthreads();
    for (int kt = 0; kt < nkt; kt++) {
        const int st = kt & 1;
        if (kt + 1 < nkt) LDG_TILE(kt + 1);
        COMPUTE(st);
        if (kt + 1 < nkt) STS_TILE(st ^ 1);
        __syncthreads();
    }

    /* epilogue */
#pragma unroll
    for (int mf = 0; mf < 4; mf++) {
#pragma unroll
        for (int nf = 0; nf < 4; nf++) {
            const int r0 = m0 + wm + mf * 16 + g;
            const int c0 = n0 + wn + nf * 8 + 2 * tg;
            const float b0 = bias[c0], b1 = bias[c0 + 1];
            float v00 = c[mf][nf][0] + b0, v01 = c[mf][nf][1] + b1;
            float v10 = c[mf][nf][2] + b0, v11 = c[mf][nf][3] + b1;
            if (EPI == 0) {
                const int which = c0 / DIMC;
                const int rem = c0 - which * DIMC;
                const int h = rem >> 6, d = rem & 63;
                float* buf = (which == 0) ? g_q : (which == 1) ? g_k : g_v;
#pragma unroll
                for (int rr = 0; rr < 2; rr++) {
                    int m = r0 + rr * 8;
                    int bidx = m / NN, n = m - bidx * NN;
                    float2 val = rr ? make_float2(v10, v11) : make_float2(v00, v01);
                    *(float2*)&buf[(((size_t)(bidx * NH + h)) * NN + n) * HD + d] = val;
                }
            } else {
                *(float2*)&Cout[(size_t)r0 * N + c0] = make_float2(v00, v01);
                *(float2*)&Cout[(size_t)(r0 + 8) * N + c0] = make_float2(v10, v11);
            }
        }
    }
#undef LDG_TILE
#undef STS_TILE
#undef COMPUTE
}

/* ------------------------------------------------------------------ */
/* weight transpose: in[R,C] -> g_wt{1,2}[C,R]                         */
/* ------------------------------------------------------------------ */
__global__ void transpose_w(const float* __restrict__ in, int R, int C, int which)
{
    __shared__ float t[32][33];
    float* out = which ? g_wt2 : g_wt1;
    const int c0 = blockIdx.x * 32, r0 = blockIdx.y * 32;
    const int tx = threadIdx.x, ty = threadIdx.y;
#pragma unroll
    for (int i = 0; i < 32; i += 8)
        t[ty + i][tx] = in[(size_t)(r0 + ty + i) * C + c0 + tx];
    __syncthreads();
#pragma unroll
    for (int i = 0; i < 32; i += 8)
        out[(size_t)(c0 + ty + i) * R + r0 + tx] = t[tx][ty + i];
}

/* ------------------------------------------------------------------ */
/* Fused attention (unchanged, known-good FFMA version)                */
/* ------------------------------------------------------------------ */
__global__ void __launch_bounds__(256) attn_kernel(const float* __restrict__ wblend)
{
    extern __shared__ float sm[];
    float* sQ = sm;             /* 64 x 65 */
    float* sK = sQ + 64 * 65;   /* 64 x 65 */
    float* sV = sK + 64 * 65;   /* 64 x 68 */
    float* sE = sV + 64 * 68;   /* 64 x 68 */
    float* sR = sE + 64 * 68;   /* 64 x 68 */
    float* sL = sR + 64 * 68;   /* 64      */

    const int tid = threadIdx.x;
    const int nt = blockIdx.x, h = blockIdx.y, bz = blockIdx.z;
    const size_t base = ((size_t)bz * NH + h) * NN * HD;
    const float* qg = g_q + base + (size_t)nt * 64 * HD;
    const float* kg = g_k + base;
    const float* vg = g_v + base;

#pragma unroll
    for (int i = 0; i < 4; i++) {
        int idx = tid + i * 256;
        int r = idx >> 4, c = (idx & 15) << 2;
        float4 v = *(const float4*)(qg + (size_t)r * HD + c);
        sQ[r * 65 + c + 0] = v.x;
        sQ[r * 65 + c + 1] = v.y;
        sQ[r * 65 + c + 2] = v.z;
        sQ[r * 65 + c + 3] = v.w;
    }
    if (tid < 64) sL[tid] = 0.f;

    float accS[16], accR[16];
#pragma unroll
    for (int i = 0; i < 16; i++) { accS[i] = 0.f; accR[i] = 0.f; }

    const int vr = tid >> 2, dc = tid & 3;
    const int rg = tid >> 4, jg = tid & 15;

    __syncthreads();

    for (int kt = 0; kt < NN / 64; kt++) {
#pragma unroll
        for (int i = 0; i < 4; i++) {
            int idx = tid + i * 256;
            int r = idx >> 4, c = (idx & 15) << 2;
            float4 vk = *(const float4*)(kg + (size_t)(kt * 64 + r) * HD + c);
            sK[r * 65 + c + 0] = vk.x;
            sK[r * 65 + c + 1] = vk.y;
            sK[r * 65 + c + 2] = vk.z;
            sK[r * 65 + c + 3] = vk.w;
            float4 vv = *(const float4*)(vg + (size_t)(kt * 64 + r) * HD + c);
            sV[r * 68 + c + 0] = vv.x;
            sV[r * 68 + c + 1] = vv.y;
            sV[r * 68 + c + 2] = vv.z;
            sV[r * 68 + c + 3] = vv.w;
        }
        __syncthreads();

        float s[4][4];
#pragma unroll
        for (int i = 0; i < 4; i++)
#pragma unroll
            for (int j = 0; j < 4; j++) s[i][j] = 0.f;

#pragma unroll 8
        for (int d = 0; d < HD; d++) {
            float qv[4], kv[4];
#pragma unroll
            for (int i = 0; i < 4; i++) qv[i] = sQ[(rg * 4 + i) * 65 + d];
#pragma unroll
            for (int j = 0; j < 4; j++) kv[j] = sK[(jg * 4 + j) * 65 + d];
#pragma unroll
            for (int i = 0; i < 4; i++)
#pragma unroll
                for (int j = 0; j < 4; j++)
                    s[i][j] = fmaf(qv[i], kv[j], s[i][j]);
        }

        float esum[4];
#pragma unroll
        for (int i = 0; i < 4; i++) {
            esum[i] = 0.f;
#pragma unroll
            for (int j = 0; j < 4; j++) {
                float sv = s[i][j] * SCALE_F;
                float e = __expf(sv);
                float rl = (sv > 0.f) ? sv * sv : 0.f;
                sE[(rg * 4 + i) * 68 + jg * 4 + j] = e;
                sR[(rg * 4 + i) * 68 + jg * 4 + j] = rl;
                esum[i] += e;
            }
        }
#pragma unroll
        for (int off = 1; off < 16; off <<= 1)
#pragma unroll
            for (int i = 0; i < 4; i++)
                esum[i] += __shfl_xor_sync(0xffffffffu, esum[i], off);
        if (jg == 0) {
#pragma unroll
            for (int i = 0; i < 4; i++) sL[rg * 4 + i] += esum[i];
        }
        __syncthreads();

#pragma unroll 4
        for (int j = 0; j < 64; j++) {
            float e = sE[vr * 68 + j];
            float rl = sR[vr * 68 + j];
#pragma unroll
            for (int q = 0; q < 4; q++) {
                float4 vv = *(const float4*)(sV + j * 68 + dc * 16 + q * 4);
                accS[q * 4 + 0] = fmaf(e, vv.x, accS[q * 4 + 0]);
                accS[q * 4 + 1] = fmaf(e, vv.y, accS[q * 4 + 1]);
                accS[q * 4 + 2] = fmaf(e, vv.z, accS[q * 4 + 2]);
                accS[q * 4 + 3] = fmaf(e, vv.w, accS[q * 4 + 3]);
                accR[q * 4 + 0] = fmaf(rl, vv.x, accR[q * 4 + 0]);
                accR[q * 4 + 1] = fmaf(rl, vv.y, accR[q * 4 + 1]);
                accR[q * 4 + 2] = fmaf(rl, vv.z, accR[q * 4 + 2]);
                accR[q * 4 + 3] = fmaf(rl, vv.w, accR[q * 4 + 3]);
            }
        }
        __syncthreads();
    }

    float w0 = wblend[0], w1 = wblend[1];
    float ws0 = 1.f / (1.f + __expf(w1 - w0));
    float ws1 = 1.f - ws0;
    float inv = ws0 / sL[vr];

    float* outp = g_att + ((size_t)(bz * NN) + nt * 64 + vr) * DIMC + h * HD + dc * 16;
#pragma unroll
    for (int q = 0; q < 4; q++) {
        float4 o;
        o.x = accS[q * 4 + 0] * inv + accR[q * 4 + 0] * ws1;
        o.y = accS[q * 4 + 1] * inv + accR[q * 4 + 1] * ws1;
        o.z = accS[q * 4 + 2] * inv + accR[q * 4 + 2] * ws1;
        o.w = accS[q * 4 + 3] * inv + accR[q * 4 + 3] * ws1;
        *(float4*)(outp + q * 4) = o;
    }
}

/* ------------------------------------------------------------------ */
extern "C" void kernel_launch(void* const* d_in, const int* in_sizes, int n_in,
                              void* d_out, int out_size)
{
    (void)in_sizes; (void)n_in; (void)out_size;
    const float* x      = (const float*)d_in[0];
    const float* qkv_w  = (const float*)d_in[1];
    const float* qkv_b  = (const float*)d_in[2];
    const float* proj_w = (const float*)d_in[3];
    const float* proj_b = (const float*)d_in[4];
    const float* w      = (const float*)d_in[5];
    float* out = (float*)d_out;

    const int attn_smem = (64 * 65 * 2 + 64 * 68 * 3 + 64) * 4; /* 85760 B */
    cudaFuncSetAttribute(tgemm<0>, cudaFuncAttributeMaxDynamicSharedMemorySize, GSM_TOTAL);
    cudaFuncSetAttribute(tgemm<1>, cudaFuncAttributeMaxDynamicSharedMemorySize, GSM_TOTAL);
    cudaFuncSetAttribute(attn_kernel, cudaFuncAttributeMaxDynamicSharedMemorySize, attn_smem);

    transpose_w<<<dim3(QKVN / 32, DIMC / 32), dim3(32, 8)>>>(qkv_w, DIMC, QKVN, 0);
    transpose_w<<<dim3(DIMC / 32, DIMC / 32), dim3(32, 8)>>>(proj_w, DIMC, DIMC, 1);

    dim3 g1(QKVN / BN, MROWS / BM);   /* 18 x 80 */
    tgemm<0><<<g1, 256, GSM_TOTAL>>>(x, qkv_b, nullptr, QKVN, DIMC);

    dim3 ga(NN / 64, NH, BB);         /* 10 x 12 x 16 */
    attn_kernel<<<ga, 256, attn_smem>>>(w);

    dim3 g2(DIMC / BN, MROWS / BM);   /* 3 x 80 */
    tgemm<1><<<g2, 256, GSM_TOTAL>>>(nullptr, proj_b, out, DIMC, DIMC);
}

// round 4
// speedup vs baseline: 4.0703x; 2.8650x over previous
#include <cuda_runtime.h>
#include <cuda_bf16.h>
#include <stdint.h>

#define DIMC 768
#define NH 12
#define HD 64
#define BB 16
#define NN 640
#define MROWS (BB * NN)      /* 10240 */
#define QKVN (3 * DIMC)      /* 2304 */
#define SCALE_F 0.125f

/* GEMM tiling */
#define BM 128
#define BN 128
#define BK 32
#define SB_STRIDE 36
#define SA_BYTES (BM * BK * 4)
#define SB_BYTES (BN * SB_STRIDE * 4)
#define STAGE_BYTES (SA_BYTES + SB_BYTES)
#define GSM_TOTAL (2 * STAGE_BYTES)

/* scratch (allocation-free rule: __device__ globals) */
#define PLANE ((size_t)BB * NH * NN * HD)
__device__ __nv_bfloat16 g_qh[PLANE];
__device__ __nv_bfloat16 g_ql[PLANE];
__device__ __nv_bfloat16 g_kh[PLANE];
__device__ __nv_bfloat16 g_kl[PLANE];
__device__ __nv_bfloat16 g_vh[PLANE];
__device__ __nv_bfloat16 g_vl[PLANE];
__device__ float g_att[(size_t)MROWS * DIMC];
__device__ float g_wt1[(size_t)QKVN * DIMC];
__device__ float g_wt2[(size_t)DIMC * DIMC];

/* ---------------- helpers ---------------- */
__device__ __forceinline__ uint32_t smem_u32(const void* p) {
    uint32_t a;
    asm("{ .reg .u64 t; cvta.to.shared.u64 t, %1; cvt.u32.u64 %0, t; }"
        : "=r"(a) : "l"(p));
    return a;
}

__device__ __forceinline__ float to_tf32(float x) {
    float r;
    asm("cvt.rna.tf32.f32 %0, %1;" : "=f"(r) : "f"(x));
    return r;
}

#define LDMATRIX_X4(r0, r1, r2, r3, addr) \
    asm volatile("ldmatrix.sync.aligned.m8n8.x4.shared.b16 {%0,%1,%2,%3}, [%4];" \
        : "=r"(r0), "=r"(r1), "=r"(r2), "=r"(r3) : "r"(addr))

#define LDMATRIX_X4_T(r0, r1, r2, r3, addr) \
    asm volatile("ldmatrix.sync.aligned.m8n8.x4.trans.shared.b16 {%0,%1,%2,%3}, [%4];" \
        : "=r"(r0), "=r"(r1), "=r"(r2), "=r"(r3) : "r"(addr))

#define MMA_TF32(C, A, B) \
    asm volatile("mma.sync.aligned.m16n8k8.row.col.f32.tf32.tf32.f32 " \
        "{%0,%1,%2,%3}, {%4,%5,%6,%7}, {%8,%9}, {%0,%1,%2,%3};" \
        : "+f"((C)[0]), "+f"((C)[1]), "+f"((C)[2]), "+f"((C)[3]) \
        : "r"((A)[0]), "r"((A)[1]), "r"((A)[2]), "r"((A)[3]), \
          "r"((B)[0]), "r"((B)[1]))

#define MMA_BF16(C, A0, A1, A2, A3, B0, B1) \
    asm volatile("mma.sync.aligned.m16n8k16.row.col.f32.bf16.bf16.f32 " \
        "{%0,%1,%2,%3}, {%4,%5,%6,%7}, {%8,%9}, {%0,%1,%2,%3};" \
        : "+f"((C)[0]), "+f"((C)[1]), "+f"((C)[2]), "+f"((C)[3]) \
        : "r"(A0), "r"(A1), "r"(A2), "r"(A3), "r"(B0), "r"(B1))

#define CP_ASYNC16(dst, src) \
    asm volatile("cp.async.cg.shared.global [%0], [%1], 16;" :: "r"(dst), "l"(src))
#define CP_COMMIT() asm volatile("cp.async.commit_group;" ::: "memory")
#define CP_WAIT1() asm volatile("cp.async.wait_group 1;" ::: "memory")
#define CP_WAIT0() asm volatile("cp.async.wait_group 0;" ::: "memory")

/* split f32 pair -> bf16x2 hi + bf16x2 lo (residual) */
__device__ __forceinline__ void pack2(float a, float b, uint32_t& hi, uint32_t& lo) {
    __nv_bfloat162 H = __floats2bfloat162_rn(a, b);
    float2 Hf = __bfloat1622float2(H);
    __nv_bfloat162 L = __floats2bfloat162_rn(a - Hf.x, b - Hf.y);
    hi = *reinterpret_cast<uint32_t*>(&H);
    lo = *reinterpret_cast<uint32_t*>(&L);
}

/* ------------------------------------------------------------------ */
/* tf32 mma.sync GEMM (same as R3)                                     */
/* EPI==0: scatter into bf16 hi/lo planes; EPI==1: dense f32 out       */
/* ------------------------------------------------------------------ */
template <int EPI>
__global__ void __launch_bounds__(256)
tgemm(const float* __restrict__ Ain, const float* __restrict__ bias,
      float* __restrict__ Cout, int N, int K)
{
    extern __shared__ char smraw[];
    const float* Ap = (EPI == 0) ? Ain : (const float*)g_att;
    const float* Bt = (EPI == 0) ? (const float*)g_wt1 : (const float*)g_wt2;

    const int tid = threadIdx.x;
    const int m0 = blockIdx.y * BM, n0 = blockIdx.x * BN;
    const int lane = tid & 31, wid = tid >> 5;
    const int wm = (wid >> 2) * 64;
    const int wn = (wid & 3) * 32;
    const int g = lane >> 2, tg = lane & 3;
    const int lr = lane & 15, half = lane >> 4;
    const int arow = tid >> 3, ac4 = tid & 7;

    float c[4][4][4];
#pragma unroll
    for (int mf = 0; mf < 4; mf++)
#pragma unroll
        for (int nf = 0; nf < 4; nf++)
#pragma unroll
            for (int r = 0; r < 4; r++) c[mf][nf][r] = 0.f;

    float4 ra[4], rb[4];
    const uint32_t sbase = smem_u32(smraw);

#define LDG_TILE(kt) do {                                                      \
    const float* Ag = Ap + (size_t)m0 * K + (kt) * BK;                         \
    const float* Bg = Bt + (size_t)n0 * K + (kt) * BK;                         \
    _Pragma("unroll")                                                          \
    for (int i = 0; i < 4; i++)                                                \
        ra[i] = *(const float4*)(Ag + (size_t)(arow + i * 32) * K + ac4 * 4);  \
    _Pragma("unroll")                                                          \
    for (int i = 0; i < 4; i++)                                                \
        rb[i] = *(const float4*)(Bg + (size_t)(arow + i * 32) * K + ac4 * 4);  \
} while (0)

#define STS_TILE(st) do {                                                      \
    char* base = smraw + (st) * STAGE_BYTES;                                   \
    _Pragma("unroll")                                                          \
    for (int i = 0; i < 4; i++) {                                              \
        int r = arow + i * 32;                                                 \
        float4 v = ra[i];                                                      \
        v.x = to_tf32(v.x); v.y = to_tf32(v.y);                                \
        v.z = to_tf32(v.z); v.w = to_tf32(v.w);                                \
        *(float4*)(base + r * 128 + ((ac4 ^ (r & 7)) * 16)) = v;               \
    }                                                                          \
    float* bb = (float*)(base + SA_BYTES);                                     \
    _Pragma("unroll")                                                          \
    for (int i = 0; i < 4; i++) {                                              \
        int r = arow + i * 32;                                                 \
        float4 v = rb[i];                                                      \
        v.x = to_tf32(v.x); v.y = to_tf32(v.y);                                \
        v.z = to_tf32(v.z); v.w = to_tf32(v.w);                                \
        *(float4*)(bb + r * SB_STRIDE + ac4 * 4) = v;                          \
    }                                                                          \
} while (0)

#define COMPUTE(st) do {                                                       \
    const uint32_t a_s = sbase + (st) * STAGE_BYTES;                           \
    const float* bsm = (const float*)(smraw + (st) * STAGE_BYTES + SA_BYTES);  \
    _Pragma("unroll")                                                          \
    for (int ks = 0; ks < 4; ks++) {                                           \
        uint32_t a[4][4];                                                      \
        _Pragma("unroll")                                                      \
        for (int mf = 0; mf < 4; mf++) {                                       \
            int r = wm + mf * 16 + lr;                                         \
            int chunk = (2 * ks + half) ^ (r & 7);                             \
            uint32_t addr = a_s + r * 128 + chunk * 16;                        \
            LDMATRIX_X4(a[mf][0], a[mf][1], a[mf][2], a[mf][3], addr);         \
        }                                                                      \
        uint32_t b[4][2];                                                      \
        _Pragma("unroll")                                                      \
        for (int nf = 0; nf < 4; nf++) {                                       \
            const uint32_t* bp = (const uint32_t*)(bsm                         \
                + (wn + nf * 8 + g) * SB_STRIDE + ks * 8 + tg);                \
            b[nf][0] = bp[0];                                                  \
            b[nf][1] = bp[4];                                                  \
        }                                                                      \
        _Pragma("unroll")                                                      \
        for (int mf = 0; mf < 4; mf++)                                         \
            _Pragma("unroll")                                                  \
            for (int nf = 0; nf < 4; nf++)                                     \
                MMA_TF32(c[mf][nf], a[mf], b[nf]);                             \
    }                                                                          \
} while (0)

    const int nkt = K / BK;
    LDG_TILE(0);
    STS_TILE(0);
    __syncthreads();
    for (int kt = 0; kt < nkt; kt++) {
        const int st = kt & 1;
        if (kt + 1 < nkt) LDG_TILE(kt + 1);
        COMPUTE(st);
        if (kt + 1 < nkt) STS_TILE(st ^ 1);
        __syncthreads();
    }

#pragma unroll
    for (int mf = 0; mf < 4; mf++) {
#pragma unroll
        for (int nf = 0; nf < 4; nf++) {
            const int r0 = m0 + wm + mf * 16 + g;
            const int c0 = n0 + wn + nf * 8 + 2 * tg;
            const float b0 = bias[c0], b1 = bias[c0 + 1];
            float v00 = c[mf][nf][0] + b0, v01 = c[mf][nf][1] + b1;
            float v10 = c[mf][nf][2] + b0, v11 = c[mf][nf][3] + b1;
            if (EPI == 0) {
                const int which = c0 / DIMC;
                const int rem = c0 - which * DIMC;
                const int h = rem >> 6, d = rem & 63;
                __nv_bfloat16* bh = (which == 0) ? g_qh : (which == 1) ? g_kh : g_vh;
                __nv_bfloat16* bl = (which == 0) ? g_ql : (which == 1) ? g_kl : g_vl;
#pragma unroll
                for (int rr = 0; rr < 2; rr++) {
                    int m = r0 + rr * 8;
                    int bidx = m / NN, n = m - bidx * NN;
                    float vx = rr ? v10 : v00, vy = rr ? v11 : v01;
                    __nv_bfloat162 H = __floats2bfloat162_rn(vx, vy);
                    float2 Hf = __bfloat1622float2(H);
                    __nv_bfloat162 L = __floats2bfloat162_rn(vx - Hf.x, vy - Hf.y);
                    size_t off = (((size_t)(bidx * NH + h)) * NN + n) * HD + d;
                    *(__nv_bfloat162*)&bh[off] = H;
                    *(__nv_bfloat162*)&bl[off] = L;
                }
            } else {
                *(float2*)&Cout[(size_t)r0 * N + c0] = make_float2(v00, v01);
                *(float2*)&Cout[(size_t)(r0 + 8) * N + c0] = make_float2(v10, v11);
            }
        }
    }
#undef LDG_TILE
#undef STS_TILE
#undef COMPUTE
}

/* ------------------------------------------------------------------ */
/* weight transpose                                                    */
/* ------------------------------------------------------------------ */
__global__ void transpose_w(const float* __restrict__ in, int R, int C, int which)
{
    __shared__ float t[32][33];
    float* out = which ? g_wt2 : g_wt1;
    const int c0 = blockIdx.x * 32, r0 = blockIdx.y * 32;
    const int tx = threadIdx.x, ty = threadIdx.y;
#pragma unroll
    for (int i = 0; i < 32; i += 8)
        t[ty + i][tx] = in[(size_t)(r0 + ty + i) * C + c0 + tx];
    __syncthreads();
#pragma unroll
    for (int i = 0; i < 32; i += 8)
        out[(size_t)(c0 + ty + i) * R + r0 + tx] = t[tx][ty + i];
}

/* ------------------------------------------------------------------ */
/* Tensor-core attention. CTA = 128 thr / 4 warps, 64 q-rows.          */
/* Per warp: 16 q-rows.  Loop 64-key tiles:                            */
/*   S = QK^T via split-bf16 (3 mma terms), exp/relu^2 in fp32,        */
/*   P -> in-register bf16 hi/lo A-fragments, PV via split-bf16.       */
/* ------------------------------------------------------------------ */
#define AS_QH 0
#define AS_QL 8192
#define AS_KV 16384          /* stage s at AS_KV + s*32768: KH,KL,VH,VL each 8KB */
#define ASM_TOTAL (AS_KV + 2 * 32768)   /* 81920 */

__device__ __forceinline__ void load_kv_tile(
    uint32_t stb, const __nv_bfloat16* kh, const __nv_bfloat16* kl,
    const __nv_bfloat16* vh, const __nv_bfloat16* vl, int kt, int tid)
{
#pragma unroll
    for (int i = 0; i < 4; i++) {
        int idx = tid + i * 128;
        int row = idx >> 3, ch = idx & 7;
        uint32_t soff = row * 128 + (((ch ^ (row & 7))) * 16);
        size_t goff = (size_t)(kt * 64 + row) * 64 + ch * 8;
        CP_ASYNC16(stb + soff,         kh + goff);
        CP_ASYNC16(stb + 8192 + soff,  kl + goff);
        CP_ASYNC16(stb + 16384 + soff, vh + goff);
        CP_ASYNC16(stb + 24576 + soff, vl + goff);
    }
}

__global__ void __launch_bounds__(128) attn2(const float* __restrict__ wblend)
{
    extern __shared__ char sm[];
    const uint32_t sb = smem_u32(sm);
    const int tid = threadIdx.x, warp = tid >> 5, lane = tid & 31;
    const int g = lane >> 2, tg = lane & 3;
    const int qt = blockIdx.x, h = blockIdx.y, b = blockIdx.z;

    const size_t pbase = ((size_t)(b * NH + h)) * NN * HD;
    const __nv_bfloat16* qhp = g_qh + pbase + (size_t)qt * 64 * HD;
    const __nv_bfloat16* qlp = g_ql + pbase + (size_t)qt * 64 * HD;
    const __nv_bfloat16* khp = g_kh + pbase;
    const __nv_bfloat16* klp = g_kl + pbase;
    const __nv_bfloat16* vhp = g_vh + pbase;
    const __nv_bfloat16* vlp = g_vl + pbase;

    /* Q tiles -> smem (plain, swizzled) */
#pragma unroll
    for (int i = 0; i < 4; i++) {
        int idx = tid + i * 128;
        int row = idx >> 3, ch = idx & 7;
        uint32_t soff = row * 128 + (((ch ^ (row & 7))) * 16);
        *(float4*)(sm + AS_QH + soff) = *(const float4*)(qhp + (size_t)row * 64 + ch * 8);
        *(float4*)(sm + AS_QL + soff) = *(const float4*)(qlp + (size_t)row * 64 + ch * 8);
    }

    load_kv_tile(sb + AS_KV, khp, klp, vhp, vlp, 0, tid);
    CP_COMMIT();

    float accE[8][4], accR[8][4];
#pragma unroll
    for (int n = 0; n < 8; n++)
#pragma unroll
        for (int r = 0; r < 4; r++) { accE[n][r] = 0.f; accR[n][r] = 0.f; }
    float ls0 = 0.f, ls1 = 0.f;
    const float w0 = wblend[0], w1 = wblend[1];

    const int qrow = warp * 16 + (lane & 15);
    const int qhalf = lane >> 4;

    for (int kt = 0; kt < NN / 64; kt++) {
        const int st = kt & 1;
        if (kt + 1 < NN / 64) {
            load_kv_tile(sb + AS_KV + (st ^ 1) * 32768, khp, klp, vhp, vlp, kt + 1, tid);
            CP_COMMIT();
            CP_WAIT1();
        } else {
            CP_WAIT0();
        }
        __syncthreads();

        const uint32_t stb = sb + AS_KV + st * 32768;

        /* Q a-frags (hi/lo) */
        uint32_t ah[4][4], al[4][4];
#pragma unroll
        for (int c = 0; c < 4; c++) {
            int chi = 2 * c + qhalf;
            uint32_t addr = sb + AS_QH + qrow * 128 + ((chi ^ (qrow & 7)) * 16);
            LDMATRIX_X4(ah[c][0], ah[c][1], ah[c][2], ah[c][3], addr);
            LDMATRIX_X4(al[c][0], al[c][1], al[c][2], al[c][3], addr + 8192);
        }

        /* S = QK^T */
        float S[8][4];
#pragma unroll
        for (int j = 0; j < 8; j++)
#pragma unroll
            for (int r = 0; r < 4; r++) S[j][r] = 0.f;

#pragma unroll
        for (int cp = 0; cp < 2; cp++) {
#pragma unroll
            for (int j = 0; j < 8; j++) {
                int krow = j * 8 + (lane & 7);
                int chi = 4 * cp + (lane >> 3);
                uint32_t addr = stb + krow * 128 + ((chi ^ (krow & 7)) * 16);
                uint32_t bh0, bh1, bh2, bh3, bl0, bl1, bl2, bl3;
                LDMATRIX_X4(bh0, bh1, bh2, bh3, addr);
                LDMATRIX_X4(bl0, bl1, bl2, bl3, addr + 8192);
                const int c0 = 2 * cp, c1 = 2 * cp + 1;
                MMA_BF16(S[j], ah[c0][0], ah[c0][1], ah[c0][2], ah[c0][3], bh0, bh1);
                MMA_BF16(S[j], ah[c0][0], ah[c0][1], ah[c0][2], ah[c0][3], bl0, bl1);
                MMA_BF16(S[j], al[c0][0], al[c0][1], al[c0][2], al[c0][3], bh0, bh1);
                MMA_BF16(S[j], ah[c1][0], ah[c1][1], ah[c1][2], ah[c1][3], bh2, bh3);
                MMA_BF16(S[j], ah[c1][0], ah[c1][1], ah[c1][2], ah[c1][3], bl2, bl3);
                MMA_BF16(S[j], al[c1][0], al[c1][1], al[c1][2], al[c1][3], bh2, bh3);
            }
        }

        /* convert S -> E (exp) and R (relu^2) bf16 hi/lo A-frags */
        uint32_t eh[4][4], el[4][4], rh[4][4], rl[4][4];
#pragma unroll
        for (int c = 0; c < 4; c++) {
            float ev[8], rv[8];
#pragma unroll
            for (int t = 0; t < 4; t++) {
                float sv = S[2 * c][t] * SCALE_F;
                ev[t] = __expf(sv);
                rv[t] = (sv > 0.f) ? sv * sv : 0.f;
            }
#pragma unroll
            for (int t = 0; t < 4; t++) {
                float sv = S[2 * c + 1][t] * SCALE_F;
                ev[4 + t] = __expf(sv);
                rv[4 + t] = (sv > 0.f) ? sv * sv : 0.f;
            }
            ls0 += (ev[0] + ev[1]) + (ev[4] + ev[5]);
            ls1 += (ev[2] + ev[3]) + (ev[6] + ev[7]);
            pack2(ev[0], ev[1], eh[c][0], el[c][0]);
            pack2(ev[2], ev[3], eh[c][1], el[c][1]);
            pack2(ev[4], ev[5], eh[c][2], el[c][2]);
            pack2(ev[6], ev[7], eh[c][3], el[c][3]);
            pack2(rv[0], rv[1], rh[c][0], rl[c][0]);
            pack2(rv[2], rv[3], rh[c][1], rl[c][1]);
            pack2(rv[4], rv[5], rh[c][2], rl[c][2]);
            pack2(rv[6], rv[7], rh[c][3], rl[c][3]);
        }

        /* PV: both branches share V fragments */
#pragma unroll
        for (int n = 0; n < 8; n++) {
#pragma unroll
            for (int cp = 0; cp < 2; cp++) {
                int vrow = 32 * cp + lane;
                uint32_t addr = stb + 16384 + vrow * 128 + ((n ^ (vrow & 7)) * 16);
                uint32_t vh0, vh1, vh2, vh3, vl0, vl1, vl2, vl3;
                LDMATRIX_X4_T(vh0, vh1, vh2, vh3, addr);
                LDMATRIX_X4_T(vl0, vl1, vl2, vl3, addr + 8192);
                const int c0 = 2 * cp, c1 = 2 * cp + 1;
                MMA_BF16(accE[n], eh[c0][0], eh[c0][1], eh[c0][2], eh[c0][3], vh0, vh1);
                MMA_BF16(accE[n], eh[c0][0], eh[c0][1], eh[c0][2], eh[c0][3], vl0, vl1);
                MMA_BF16(accE[n], el[c0][0], el[c0][1], el[c0][2], el[c0][3], vh0, vh1);
                MMA_BF16(accR[n], rh[c0][0], rh[c0][1], rh[c0][2], rh[c0][3], vh0, vh1);
                MMA_BF16(accR[n], rh[c0][0], rh[c0][1], rh[c0][2], rh[c0][3], vl0, vl1);
                MMA_BF16(accR[n], rl[c0][0], rl[c0][1], rl[c0][2], rl[c0][3], vh0, vh1);
                MMA_BF16(accE[n], eh[c1][0], eh[c1][1], eh[c1][2], eh[c1][3], vh2, vh3);
                MMA_BF16(accE[n], eh[c1][0], eh[c1][1], eh[c1][2], eh[c1][3], vl2, vl3);
                MMA_BF16(accE[n], el[c1][0], el[c1][1], el[c1][2], el[c1][3], vh2, vh3);
                MMA_BF16(accR[n], rh[c1][0], rh[c1][1], rh[c1][2], rh[c1][3], vh2, vh3);
                MMA_BF16(accR[n], rh[c1][0], rh[c1][1], rh[c1][2], rh[c1][3], vl2, vl3);
                MMA_BF16(accR[n], rl[c1][0], rl[c1][1], rl[c1][2], rl[c1][3], vh2, vh3);
            }
        }
        __syncthreads();
    }

    /* row-sum reduce over the 4 tg lanes */
    ls0 += __shfl_xor_sync(0xffffffffu, ls0, 1);
    ls0 += __shfl_xor_sync(0xffffffffu, ls0, 2);
    ls1 += __shfl_xor_sync(0xffffffffu, ls1, 1);
    ls1 += __shfl_xor_sync(0xffffffffu, ls1, 2);

    const float ws0 = 1.f / (1.f + __expf(w1 - w0));
    const float ws1 = 1.f - ws0;
    const float inv0 = ws0 / ls0;
    const float inv1 = ws0 / ls1;

    const int row0 = b * NN + qt * 64 + warp * 16 + g;
    float* out0 = g_att + (size_t)row0 * DIMC + h * HD;
    float* out1 = out0 + (size_t)8 * DIMC;
#pragma unroll
    for (int n = 0; n < 8; n++) {
        float2 o0 = make_float2(accE[n][0] * inv0 + accR[n][0] * ws1,
                                accE[n][1] * inv0 + accR[n][1] * ws1);
        float2 o1 = make_float2(accE[n][2] * inv1 + accR[n][2] * ws1,
                                accE[n][3] * inv1 + accR[n][3] * ws1);
        *(float2*)(out0 + n * 8 + 2 * tg) = o0;
        *(float2*)(out1 + n * 8 + 2 * tg) = o1;
    }
}

/* ------------------------------------------------------------------ */
extern "C" void kernel_launch(void* const* d_in, const int* in_sizes, int n_in,
                              void* d_out, int out_size)
{
    (void)in_sizes; (void)n_in; (void)out_size;
    const float* x      = (const float*)d_in[0];
    const float* qkv_w  = (const float*)d_in[1];
    const float* qkv_b  = (const float*)d_in[2];
    const float* proj_w = (const float*)d_in[3];
    const float* proj_b = (const float*)d_in[4];
    const float* w      = (const float*)d_in[5];
    float* out = (float*)d_out;

    cudaFuncSetAttribute(tgemm<0>, cudaFuncAttributeMaxDynamicSharedMemorySize, GSM_TOTAL);
    cudaFuncSetAttribute(tgemm<1>, cudaFuncAttributeMaxDynamicSharedMemorySize, GSM_TOTAL);
    cudaFuncSetAttribute(attn2, cudaFuncAttributeMaxDynamicSharedMemorySize, ASM_TOTAL);

    transpose_w<<<dim3(QKVN / 32, DIMC / 32), dim3(32, 8)>>>(qkv_w, DIMC, QKVN, 0);
    transpose_w<<<dim3(DIMC / 32, DIMC / 32), dim3(32, 8)>>>(proj_w, DIMC, DIMC, 1);

    dim3 g1(QKVN / BN, MROWS / BM);   /* 18 x 80 */
    tgemm<0><<<g1, 256, GSM_TOTAL>>>(x, qkv_b, nullptr, QKVN, DIMC);

    dim3 ga(NN / 64, NH, BB);         /* 10 x 12 x 16 */
    attn2<<<ga, 128, ASM_TOTAL>>>(w);

    dim3 g2(DIMC / BN, MROWS / BM);   /* 3 x 80 */
    tgemm<1><<<g2, 256, GSM_TOTAL>>>(nullptr, proj_b, out, DIMC, DIMC);
}

// round 5
// speedup vs baseline: 4.7230x; 1.1604x over previous
#include <cuda_runtime.h>
#include <cuda_bf16.h>
#include <stdint.h>

#define DIMC 768
#define NH 12
#define HD 64
#define BB 16
#define NN 640
#define MROWS (BB * NN)      /* 10240 */
#define QKVN (3 * DIMC)      /* 2304 */
#define SCALE_F 0.125f

/* GEMM tiling */
#define BM 128
#define BN 128
#define BK 32
#define SB_STRIDE 36
#define GST 34816            /* stage: A 16384 + B 18432 */
#define GSM_TOTAL (3 * GST)  /* 104448 */

/* scratch (allocation-free rule: __device__ globals) */
#define PLANE ((size_t)BB * NH * NN * HD)
__device__ float g_qf[PLANE];
__device__ float g_kf[PLANE];
__device__ __nv_bfloat16 g_vh[PLANE];
__device__ __nv_bfloat16 g_vl[PLANE];
__device__ float g_att[(size_t)MROWS * DIMC];
__device__ float g_xt[(size_t)MROWS * DIMC];
__device__ float g_wt1[(size_t)QKVN * DIMC];
__device__ float g_wt2[(size_t)DIMC * DIMC];

/* ---------------- helpers ---------------- */
__device__ __forceinline__ uint32_t smem_u32(const void* p) {
    uint32_t a;
    asm("{ .reg .u64 t; cvta.to.shared.u64 t, %1; cvt.u32.u64 %0, t; }"
        : "=r"(a) : "l"(p));
    return a;
}

__device__ __forceinline__ float to_tf32(float x) {
    float r;
    asm("cvt.rna.tf32.f32 %0, %1;" : "=f"(r) : "f"(x));
    return r;
}

#define LDMATRIX_X4(r0, r1, r2, r3, addr) \
    asm volatile("ldmatrix.sync.aligned.m8n8.x4.shared.b16 {%0,%1,%2,%3}, [%4];" \
        : "=r"(r0), "=r"(r1), "=r"(r2), "=r"(r3) : "r"(addr))

#define LDMATRIX_X4_T(r0, r1, r2, r3, addr) \
    asm volatile("ldmatrix.sync.aligned.m8n8.x4.trans.shared.b16 {%0,%1,%2,%3}, [%4];" \
        : "=r"(r0), "=r"(r1), "=r"(r2), "=r"(r3) : "r"(addr))

#define MMA_TF32(C, A, B) \
    asm volatile("mma.sync.aligned.m16n8k8.row.col.f32.tf32.tf32.f32 " \
        "{%0,%1,%2,%3}, {%4,%5,%6,%7}, {%8,%9}, {%0,%1,%2,%3};" \
        : "+f"((C)[0]), "+f"((C)[1]), "+f"((C)[2]), "+f"((C)[3]) \
        : "r"((A)[0]), "r"((A)[1]), "r"((A)[2]), "r"((A)[3]), \
          "r"((B)[0]), "r"((B)[1]))

#define MMA_BF16(C, A0, A1, A2, A3, B0, B1) \
    asm volatile("mma.sync.aligned.m16n8k16.row.col.f32.bf16.bf16.f32 " \
        "{%0,%1,%2,%3}, {%4,%5,%6,%7}, {%8,%9}, {%0,%1,%2,%3};" \
        : "+f"((C)[0]), "+f"((C)[1]), "+f"((C)[2]), "+f"((C)[3]) \
        : "r"(A0), "r"(A1), "r"(A2), "r"(A3), "r"(B0), "r"(B1))

#define CP_ASYNC16(dst, src) \
    asm volatile("cp.async.cg.shared.global [%0], [%1], 16;" :: "r"(dst), "l"(src))
#define CP_COMMIT() asm volatile("cp.async.commit_group;" ::: "memory")
#define CP_WAIT1() asm volatile("cp.async.wait_group 1;" ::: "memory")
#define CP_WAIT0() asm volatile("cp.async.wait_group 0;" ::: "memory")

__device__ __forceinline__ void pack2(float a, float b, uint32_t& hi, uint32_t& lo) {
    __nv_bfloat162 H = __floats2bfloat162_rn(a, b);
    float2 Hf = __bfloat1622float2(H);
    __nv_bfloat162 L = __floats2bfloat162_rn(a - Hf.x, b - Hf.y);
    hi = *reinterpret_cast<uint32_t*>(&H);
    lo = *reinterpret_cast<uint32_t*>(&L);
}

/* ------------------------------------------------------------------ */
/* prep: round x to tf32 into g_xt                                     */
/* ------------------------------------------------------------------ */
__global__ void round_x(const float* __restrict__ x)
{
    size_t idx = (size_t)blockIdx.x * 256 + threadIdx.x;
    float4 v = ((const float4*)x)[idx];
    v.x = to_tf32(v.x); v.y = to_tf32(v.y);
    v.z = to_tf32(v.z); v.w = to_tf32(v.w);
    ((float4*)g_xt)[idx] = v;
}

/* weight transpose with tf32 rounding: in[R,C] -> g_wt{1,2}[C,R] */
__global__ void transpose_w(const float* __restrict__ in, int R, int C, int which)
{
    __shared__ float t[32][33];
    float* out = which ? g_wt2 : g_wt1;
    const int c0 = blockIdx.x * 32, r0 = blockIdx.y * 32;
    const int tx = threadIdx.x, ty = threadIdx.y;
#pragma unroll
    for (int i = 0; i < 32; i += 8)
        t[ty + i][tx] = in[(size_t)(r0 + ty + i) * C + c0 + tx];
    __syncthreads();
#pragma unroll
    for (int i = 0; i < 32; i += 8)
        out[(size_t)(c0 + ty + i) * R + r0 + tx] = to_tf32(t[tx][ty + i]);
}

/* ------------------------------------------------------------------ */
/* tf32 mma.sync GEMM with cp.async 3-stage pipeline.                  */
/* Inputs pre-rounded to tf32 (no cvt in kernel).                      */
/* EPI==0: A=g_xt, B=g_wt1 -> q/k f32 planes + v bf16 hi/lo planes     */
/* EPI==1: A=g_att, B=g_wt2 -> dense f32 out                           */
/* ------------------------------------------------------------------ */
template <int EPI>
__global__ void __launch_bounds__(256)
tgemm(const float* __restrict__ bias, float* __restrict__ Cout, int N, int K)
{
    extern __shared__ char smraw[];
    const float* Ap = (EPI == 0) ? (const float*)g_xt : (const float*)g_att;
    const float* Bt = (EPI == 0) ? (const float*)g_wt1 : (const float*)g_wt2;

    const int tid = threadIdx.x;
    const int m0 = blockIdx.y * BM, n0 = blockIdx.x * BN;
    const int lane = tid & 31, wid = tid >> 5;
    const int wm = (wid >> 2) * 64;
    const int wn = (wid & 3) * 32;
    const int g = lane >> 2, tg = lane & 3;
    const int lr = lane & 15, half = lane >> 4;
    const int arow = tid >> 3, ac = tid & 7;
    const uint32_t sbase = smem_u32(smraw);

    float c[4][4][4];
#pragma unroll
    for (int mf = 0; mf < 4; mf++)
#pragma unroll
        for (int nf = 0; nf < 4; nf++)
#pragma unroll
            for (int r = 0; r < 4; r++) c[mf][nf][r] = 0.f;

#define LOAD_TILE(kt, st) do {                                                 \
    const float* Ag = Ap + (size_t)m0 * K + (kt) * BK;                         \
    const float* Bg = Bt + (size_t)n0 * K + (kt) * BK;                         \
    uint32_t base = sbase + (st) * GST;                                        \
    _Pragma("unroll")                                                          \
    for (int i = 0; i < 4; i++) {                                              \
        int r = arow + i * 32;                                                 \
        CP_ASYNC16(base + r * 128 + ((ac ^ (r & 7)) * 16),                     \
                   Ag + (size_t)r * K + ac * 4);                               \
        CP_ASYNC16(base + 16384 + r * 144 + ac * 16,                           \
                   Bg + (size_t)r * K + ac * 4);                               \
    }                                                                          \
} while (0)

#define COMPUTE(st) do {                                                       \
    const uint32_t a_s = sbase + (st) * GST;                                   \
    const float* bsm = (const float*)(smraw + (st) * GST + 16384);             \
    _Pragma("unroll")                                                          \
    for (int ks = 0; ks < 4; ks++) {                                           \
        uint32_t a[4][4];                                                      \
        _Pragma("unroll")                                                      \
        for (int mf = 0; mf < 4; mf++) {                                       \
            int r = wm + mf * 16 + lr;                                         \
            int chunk = (2 * ks + half) ^ (r & 7);                             \
            uint32_t addr = a_s + r * 128 + chunk * 16;                        \
            LDMATRIX_X4(a[mf][0], a[mf][1], a[mf][2], a[mf][3], addr);         \
        }                                                                      \
        uint32_t b[4][2];                                                      \
        _Pragma("unroll")                                                      \
        for (int nf = 0; nf < 4; nf++) {                                       \
            const uint32_t* bp = (const uint32_t*)(bsm                         \
                + (wn + nf * 8 + g) * SB_STRIDE + ks * 8 + tg);                \
            b[nf][0] = bp[0];                                                  \
            b[nf][1] = bp[4];                                                  \
        }                                                                      \
        _Pragma("unroll")                                                      \
        for (int mf = 0; mf < 4; mf++)                                         \
            _Pragma("unroll")                                                  \
            for (int nf = 0; nf < 4; nf++)                                     \
                MMA_TF32(c[mf][nf], a[mf], b[nf]);                             \
    }                                                                          \
} while (0)

    const int nkt = K / BK;    /* 24 */
    LOAD_TILE(0, 0); CP_COMMIT();
    LOAD_TILE(1, 1); CP_COMMIT();

    for (int kt = 0; kt < nkt; kt++) {
        const int st = kt % 3;
        if (kt + 1 < nkt) CP_WAIT1(); else CP_WAIT0();
        __syncthreads();
        COMPUTE(st);
        if (kt + 2 < nkt) {
            LOAD_TILE(kt + 2, (kt + 2) % 3);
            CP_COMMIT();
        }
    }

    /* epilogue */
#pragma unroll
    for (int mf = 0; mf < 4; mf++) {
#pragma unroll
        for (int nf = 0; nf < 4; nf++) {
            const int r0 = m0 + wm + mf * 16 + g;
            const int c0 = n0 + wn + nf * 8 + 2 * tg;
            const float b0 = bias[c0], b1 = bias[c0 + 1];
            float v00 = c[mf][nf][0] + b0, v01 = c[mf][nf][1] + b1;
            float v10 = c[mf][nf][2] + b0, v11 = c[mf][nf][3] + b1;
            if (EPI == 0) {
                const int which = c0 / DIMC;
                const int rem = c0 - which * DIMC;
                const int h = rem >> 6, d = rem & 63;
#pragma unroll
                for (int rr = 0; rr < 2; rr++) {
                    int m = r0 + rr * 8;
                    int bidx = m / NN, n = m - bidx * NN;
                    float vx = rr ? v10 : v00, vy = rr ? v11 : v01;
                    size_t off = (((size_t)(bidx * NH + h)) * NN + n) * HD + d;
                    if (which < 2) {
                        float* pf = which ? g_kf : g_qf;
                        *(float2*)&pf[off] = make_float2(to_tf32(vx), to_tf32(vy));
                    } else {
                        __nv_bfloat162 H = __floats2bfloat162_rn(vx, vy);
                        float2 Hf = __bfloat1622float2(H);
                        __nv_bfloat162 L = __floats2bfloat162_rn(vx - Hf.x, vy - Hf.y);
                        *(__nv_bfloat162*)&g_vh[off] = H;
                        *(__nv_bfloat162*)&g_vl[off] = L;
                    }
                }
            } else {
                *(float2*)&Cout[(size_t)r0 * N + c0] = make_float2(v00, v01);
                *(float2*)&Cout[(size_t)(r0 + 8) * N + c0] = make_float2(v10, v11);
            }
        }
    }
#undef LOAD_TILE
#undef COMPUTE
}

/* ------------------------------------------------------------------ */
/* Attention v3: QK^T in tf32 (q/k f32 tf32-rounded), PV 3-term bf16.  */
/* CTA = 128 thr / 4 warps, 64 q-rows, 16 per warp.                    */
/* smem: Q (2 halves, 16KB) + 2 stages x (K 17408 + VH 8192 + VL 8192) */
/* ------------------------------------------------------------------ */
#define AS_KV 16384
#define KVSTAGE 33792
#define ASM_TOTAL (AS_KV + 2 * KVSTAGE)   /* 83968 */
#define KSTRIDE 68                        /* floats; 272 B */

__device__ __forceinline__ void load_kv_tile(
    uint32_t stb, const float* kf,
    const __nv_bfloat16* vh, const __nv_bfloat16* vl, int kt, int tid)
{
#pragma unroll
    for (int i = 0; i < 8; i++) {         /* K: 64 rows x 16 chunks */
        int idx = tid + i * 128;
        int row = idx >> 4, ch = idx & 15;
        CP_ASYNC16(stb + row * 272 + ch * 16,
                   kf + (size_t)(kt * 64 + row) * 64 + ch * 4);
    }
#pragma unroll
    for (int i = 0; i < 4; i++) {         /* VH/VL: 64 rows x 8 chunks each */
        int idx = tid + i * 128;
        int row = idx >> 3, ch = idx & 7;
        uint32_t soff = row * 128 + ((ch ^ (row & 7)) * 16);
        size_t goff = (size_t)(kt * 64 + row) * 64 + ch * 8;
        CP_ASYNC16(stb + 17408 + soff,        vh + goff);
        CP_ASYNC16(stb + 17408 + 8192 + soff, vl + goff);
    }
}

__global__ void __launch_bounds__(128) attn3(const float* __restrict__ wblend)
{
    extern __shared__ char sm[];
    const uint32_t sb = smem_u32(sm);
    const int tid = threadIdx.x, warp = tid >> 5, lane = tid & 31;
    const int g = lane >> 2, tg = lane & 3;
    const int qt = blockIdx.x, h = blockIdx.y, b = blockIdx.z;

    const size_t pbase = ((size_t)(b * NH + h)) * NN * HD;
    const float* qfp = g_qf + pbase + (size_t)qt * 64 * HD;
    const float* kfp = g_kf + pbase;
    const __nv_bfloat16* vhp = g_vh + pbase;
    const __nv_bfloat16* vlp = g_vl + pbase;

    /* Q: 64 rows x 16 chunks -> two swizzled 8KB halves */
#pragma unroll
    for (int i = 0; i < 8; i++) {
        int idx = tid + i * 128;
        int row = idx >> 4, ch = idx & 15;
        int hh = ch >> 3, c2 = ch & 7;
        CP_ASYNC16(sb + hh * 8192 + row * 128 + ((c2 ^ (row & 7)) * 16),
                   qfp + (size_t)row * 64 + ch * 4);
    }
    load_kv_tile(sb + AS_KV, kfp, vhp, vlp, 0, tid);
    CP_COMMIT();

    float accE[8][4], accR[8][4];
#pragma unroll
    for (int n = 0; n < 8; n++)
#pragma unroll
        for (int r = 0; r < 4; r++) { accE[n][r] = 0.f; accR[n][r] = 0.f; }
    float ls0 = 0.f, ls1 = 0.f;
    const float w0 = wblend[0], w1 = wblend[1];

    const int qrow = warp * 16 + (lane & 15);
    const int qh16 = lane >> 4;

    for (int kt = 0; kt < NN / 64; kt++) {
        const int st = kt & 1;
        if (kt + 1 < NN / 64) {
            load_kv_tile(sb + AS_KV + (st ^ 1) * KVSTAGE, kfp, vhp, vlp, kt + 1, tid);
            CP_COMMIT();
            CP_WAIT1();
        } else {
            CP_WAIT0();
        }
        __syncthreads();

        const uint32_t stb = sb + AS_KV + st * KVSTAGE;
        const float* Ks = (const float*)(sm + AS_KV + st * KVSTAGE);

        /* S = QK^T in tf32 */
        float S[8][4];
#pragma unroll
        for (int j = 0; j < 8; j++)
#pragma unroll
            for (int r = 0; r < 4; r++) S[j][r] = 0.f;

#pragma unroll
        for (int ks = 0; ks < 8; ks++) {
            const int hh = ks >> 2, k2 = ks & 3;
            uint32_t a[4];
            uint32_t addr = sb + hh * 8192 + qrow * 128
                          + (((2 * k2 + qh16) ^ (qrow & 7)) * 16);
            LDMATRIX_X4(a[0], a[1], a[2], a[3], addr);
#pragma unroll
            for (int j = 0; j < 8; j++) {
                const uint32_t* bp = (const uint32_t*)(Ks + (j * 8 + g) * KSTRIDE
                                                       + ks * 8 + tg);
                uint32_t bfr[2];
                bfr[0] = bp[0];
                bfr[1] = bp[4];
                MMA_TF32(S[j], a, bfr);
            }
        }

        /* convert S -> E (exp), R (relu^2) bf16 hi/lo A-frags */
        uint32_t eh[4][4], el[4][4], rh[4][4], rl[4][4];
#pragma unroll
        for (int c = 0; c < 4; c++) {
            float ev[8], rv[8];
#pragma unroll
            for (int t = 0; t < 4; t++) {
                float sv = S[2 * c][t] * SCALE_F;
                ev[t] = __expf(sv);
                rv[t] = (sv > 0.f) ? sv * sv : 0.f;
            }
#pragma unroll
            for (int t = 0; t < 4; t++) {
                float sv = S[2 * c + 1][t] * SCALE_F;
                ev[4 + t] = __expf(sv);
                rv[4 + t] = (sv > 0.f) ? sv * sv : 0.f;
            }
            ls0 += (ev[0] + ev[1]) + (ev[4] + ev[5]);
            ls1 += (ev[2] + ev[3]) + (ev[6] + ev[7]);
            pack2(ev[0], ev[1], eh[c][0], el[c][0]);
            pack2(ev[2], ev[3], eh[c][1], el[c][1]);
            pack2(ev[4], ev[5], eh[c][2], el[c][2]);
            pack2(ev[6], ev[7], eh[c][3], el[c][3]);
            pack2(rv[0], rv[1], rh[c][0], rl[c][0]);
            pack2(rv[2], rv[3], rh[c][1], rl[c][1]);
            pack2(rv[4], rv[5], rh[c][2], rl[c][2]);
            pack2(rv[6], rv[7], rh[c][3], rl[c][3]);
        }

        /* PV: both branches share V fragments (3-term split bf16) */
#pragma unroll
        for (int n = 0; n < 8; n++) {
#pragma unroll
            for (int cp = 0; cp < 2; cp++) {
                int vrow = 32 * cp + lane;
                uint32_t addr = stb + 17408 + vrow * 128 + ((n ^ (vrow & 7)) * 16);
                uint32_t vh0, vh1, vh2, vh3, vl0, vl1, vl2, vl3;
                LDMATRIX_X4_T(vh0, vh1, vh2, vh3, addr);
                LDMATRIX_X4_T(vl0, vl1, vl2, vl3, addr + 8192);
                const int c0 = 2 * cp, c1 = 2 * cp + 1;
                MMA_BF16(accE[n], eh[c0][0], eh[c0][1], eh[c0][2], eh[c0][3], vh0, vh1);
                MMA_BF16(accE[n], eh[c0][0], eh[c0][1], eh[c0][2], eh[c0][3], vl0, vl1);
                MMA_BF16(accE[n], el[c0][0], el[c0][1], el[c0][2], el[c0][3], vh0, vh1);
                MMA_BF16(accR[n], rh[c0][0], rh[c0][1], rh[c0][2], rh[c0][3], vh0, vh1);
                MMA_BF16(accR[n], rh[c0][0], rh[c0][1], rh[c0][2], rh[c0][3], vl0, vl1);
                MMA_BF16(accR[n], rl[c0][0], rl[c0][1], rl[c0][2], rl[c0][3], vh0, vh1);
                MMA_BF16(accE[n], eh[c1][0], eh[c1][1], eh[c1][2], eh[c1][3], vh2, vh3);
                MMA_BF16(accE[n], eh[c1][0], eh[c1][1], eh[c1][2], eh[c1][3], vl2, vl3);
                MMA_BF16(accE[n], el[c1][0], el[c1][1], el[c1][2], el[c1][3], vh2, vh3);
                MMA_BF16(accR[n], rh[c1][0], rh[c1][1], rh[c1][2], rh[c1][3], vh2, vh3);
                MMA_BF16(accR[n], rh[c1][0], rh[c1][1], rh[c1][2], rh[c1][3], vl2, vl3);
                MMA_BF16(accR[n], rl[c1][0], rl[c1][1], rl[c1][2], rl[c1][3], vh2, vh3);
            }
        }
        __syncthreads();
    }

    ls0 += __shfl_xor_sync(0xffffffffu, ls0, 1);
    ls0 += __shfl_xor_sync(0xffffffffu, ls0, 2);
    ls1 += __shfl_xor_sync(0xffffffffu, ls1, 1);
    ls1 += __shfl_xor_sync(0xffffffffu, ls1, 2);

    const float ws0 = 1.f / (1.f + __expf(w1 - w0));
    const float ws1 = 1.f - ws0;
    const float inv0 = ws0 / ls0;
    const float inv1 = ws0 / ls1;

    const int row0 = b * NN + qt * 64 + warp * 16 + g;
    float* out0 = g_att + (size_t)row0 * DIMC + h * HD;
    float* out1 = out0 + (size_t)8 * DIMC;
#pragma unroll
    for (int n = 0; n < 8; n++) {
        float2 o0, o1;
        o0.x = to_tf32(accE[n][0] * inv0 + accR[n][0] * ws1);
        o0.y = to_tf32(accE[n][1] * inv0 + accR[n][1] * ws1);
        o1.x = to_tf32(accE[n][2] * inv1 + accR[n][2] * ws1);
        o1.y = to_tf32(accE[n][3] * inv1 + accR[n][3] * ws1);
        *(float2*)(out0 + n * 8 + 2 * tg) = o0;
        *(float2*)(out1 + n * 8 + 2 * tg) = o1;
    }
}

/* ------------------------------------------------------------------ */
extern "C" void kernel_launch(void* const* d_in, const int* in_sizes, int n_in,
                              void* d_out, int out_size)
{
    (void)in_sizes; (void)n_in; (void)out_size;
    const float* x      = (const float*)d_in[0];
    const float* qkv_w  = (const float*)d_in[1];
    const float* qkv_b  = (const float*)d_in[2];
    const float* proj_w = (const float*)d_in[3];
    const float* proj_b = (const float*)d_in[4];
    const float* w      = (const float*)d_in[5];
    float* out = (float*)d_out;

    cudaFuncSetAttribute(tgemm<0>, cudaFuncAttributeMaxDynamicSharedMemorySize, GSM_TOTAL);
    cudaFuncSetAttribute(tgemm<1>, cudaFuncAttributeMaxDynamicSharedMemorySize, GSM_TOTAL);
    cudaFuncSetAttribute(attn3, cudaFuncAttributeMaxDynamicSharedMemorySize, ASM_TOTAL);

    round_x<<<MROWS * DIMC / 1024, 256>>>(x);
    transpose_w<<<dim3(QKVN / 32, DIMC / 32), dim3(32, 8)>>>(qkv_w, DIMC, QKVN, 0);
    transpose_w<<<dim3(DIMC / 32, DIMC / 32), dim3(32, 8)>>>(proj_w, DIMC, DIMC, 1);

    dim3 g1(QKVN / BN, MROWS / BM);   /* 18 x 80 */
    tgemm<0><<<g1, 256, GSM_TOTAL>>>(qkv_b, nullptr, QKVN, DIMC);

    dim3 ga(NN / 64, NH, BB);         /* 10 x 12 x 16 */
    attn3<<<ga, 128, ASM_TOTAL>>>(w);

    dim3 g2(DIMC / BN, MROWS / BM);   /* 3 x 80 */
    tgemm<1><<<g2, 256, GSM_TOTAL>>>(proj_b, out, DIMC, DIMC);
}

// round 6
// speedup vs baseline: 5.0061x; 1.0599x over previous
#include <cuda_runtime.h>
#include <cuda_bf16.h>
#include <stdint.h>

#define DIMC 768
#define NH 12
#define HD 64
#define BB 16
#define NN 640
#define MROWS (BB * NN)      /* 10240 */
#define QKVN (3 * DIMC)      /* 2304 */
#define SCALE_F 0.125f

/* GEMM tiling */
#define BM 128
#define BN 128
#define BK 32
#define SB_STRIDE 36
#define GST 34816            /* stage: A 16384 + B 18432 */
#define GSM_TOTAL (3 * GST)  /* 104448 */

/* scratch (allocation-free rule: __device__ globals) */
#define PLANE ((size_t)BB * NH * NN * HD)
__device__ float g_qf[PLANE];
__device__ float g_kf[PLANE];
__device__ float g_vf[PLANE];
__device__ float g_att[(size_t)MROWS * DIMC];
__device__ float g_xt[(size_t)MROWS * DIMC];
__device__ float g_wt1[(size_t)QKVN * DIMC];
__device__ float g_wt2[(size_t)DIMC * DIMC];

/* ---------------- helpers ---------------- */
__device__ __forceinline__ uint32_t smem_u32(const void* p) {
    uint32_t a;
    asm("{ .reg .u64 t; cvta.to.shared.u64 t, %1; cvt.u32.u64 %0, t; }"
        : "=r"(a) : "l"(p));
    return a;
}

__device__ __forceinline__ float to_tf32(float x) {
    float r;
    asm("cvt.rna.tf32.f32 %0, %1;" : "=f"(r) : "f"(x));
    return r;
}

#define LDMATRIX_X4(r0, r1, r2, r3, addr) \
    asm volatile("ldmatrix.sync.aligned.m8n8.x4.shared.b16 {%0,%1,%2,%3}, [%4];" \
        : "=r"(r0), "=r"(r1), "=r"(r2), "=r"(r3) : "r"(addr))

#define MMA_TF32(C, A, B) \
    asm volatile("mma.sync.aligned.m16n8k8.row.col.f32.tf32.tf32.f32 " \
        "{%0,%1,%2,%3}, {%4,%5,%6,%7}, {%8,%9}, {%0,%1,%2,%3};" \
        : "+f"((C)[0]), "+f"((C)[1]), "+f"((C)[2]), "+f"((C)[3]) \
        : "r"((A)[0]), "r"((A)[1]), "r"((A)[2]), "r"((A)[3]), \
          "r"((B)[0]), "r"((B)[1]))

#define CP_ASYNC16(dst, src) \
    asm volatile("cp.async.cg.shared.global [%0], [%1], 16;" :: "r"(dst), "l"(src))
#define CP_COMMIT() asm volatile("cp.async.commit_group;" ::: "memory")
#define CP_WAIT1() asm volatile("cp.async.wait_group 1;" ::: "memory")
#define CP_WAIT0() asm volatile("cp.async.wait_group 0;" ::: "memory")

/* ------------------------------------------------------------------ */
/* prep kernels                                                        */
/* ------------------------------------------------------------------ */
__global__ void round_x(const float* __restrict__ x)
{
    size_t idx = (size_t)blockIdx.x * 256 + threadIdx.x;
    float4 v = ((const float4*)x)[idx];
    v.x = to_tf32(v.x); v.y = to_tf32(v.y);
    v.z = to_tf32(v.z); v.w = to_tf32(v.w);
    ((float4*)g_xt)[idx] = v;
}

__global__ void transpose_w(const float* __restrict__ in, int R, int C, int which)
{
    __shared__ float t[32][33];
    float* out = which ? g_wt2 : g_wt1;
    const int c0 = blockIdx.x * 32, r0 = blockIdx.y * 32;
    const int tx = threadIdx.x, ty = threadIdx.y;
#pragma unroll
    for (int i = 0; i < 32; i += 8)
        t[ty + i][tx] = in[(size_t)(r0 + ty + i) * C + c0 + tx];
    __syncthreads();
#pragma unroll
    for (int i = 0; i < 32; i += 8)
        out[(size_t)(c0 + ty + i) * R + r0 + tx] = to_tf32(t[tx][ty + i]);
}

/* ------------------------------------------------------------------ */
/* tf32 mma.sync GEMM with cp.async 3-stage pipeline (same as R5).     */
/* EPI==0: -> q/k/v tf32-rounded f32 planes                            */
/* EPI==1: -> dense f32 out                                            */
/* ------------------------------------------------------------------ */
template <int EPI>
__global__ void __launch_bounds__(256)
tgemm(const float* __restrict__ bias, float* __restrict__ Cout, int N, int K)
{
    extern __shared__ char smraw[];
    const float* Ap = (EPI == 0) ? (const float*)g_xt : (const float*)g_att;
    const float* Bt = (EPI == 0) ? (const float*)g_wt1 : (const float*)g_wt2;

    const int tid = threadIdx.x;
    const int m0 = blockIdx.y * BM, n0 = blockIdx.x * BN;
    const int lane = tid & 31, wid = tid >> 5;
    const int wm = (wid >> 2) * 64;
    const int wn = (wid & 3) * 32;
    const int g = lane >> 2, tg = lane & 3;
    const int lr = lane & 15, half = lane >> 4;
    const int arow = tid >> 3, ac = tid & 7;
    const uint32_t sbase = smem_u32(smraw);

    float c[4][4][4];
#pragma unroll
    for (int mf = 0; mf < 4; mf++)
#pragma unroll
        for (int nf = 0; nf < 4; nf++)
#pragma unroll
            for (int r = 0; r < 4; r++) c[mf][nf][r] = 0.f;

#define LOAD_TILE(kt, st) do {                                                 \
    const float* Ag = Ap + (size_t)m0 * K + (kt) * BK;                         \
    const float* Bg = Bt + (size_t)n0 * K + (kt) * BK;                         \
    uint32_t base = sbase + (st) * GST;                                        \
    _Pragma("unroll")                                                          \
    for (int i = 0; i < 4; i++) {                                              \
        int r = arow + i * 32;                                                 \
        CP_ASYNC16(base + r * 128 + ((ac ^ (r & 7)) * 16),                     \
                   Ag + (size_t)r * K + ac * 4);                               \
        CP_ASYNC16(base + 16384 + r * 144 + ac * 16,                           \
                   Bg + (size_t)r * K + ac * 4);                               \
    }                                                                          \
} while (0)

#define COMPUTE(st) do {                                                       \
    const uint32_t a_s = sbase + (st) * GST;                                   \
    const float* bsm = (const float*)(smraw + (st) * GST + 16384);             \
    _Pragma("unroll")                                                          \
    for (int ks = 0; ks < 4; ks++) {                                           \
        uint32_t a[4][4];                                                      \
        _Pragma("unroll")                                                      \
        for (int mf = 0; mf < 4; mf++) {                                       \
            int r = wm + mf * 16 + lr;                                         \
            int chunk = (2 * ks + half) ^ (r & 7);                             \
            uint32_t addr = a_s + r * 128 + chunk * 16;                        \
            LDMATRIX_X4(a[mf][0], a[mf][1], a[mf][2], a[mf][3], addr);         \
        }                                                                      \
        uint32_t b[4][2];                                                      \
        _Pragma("unroll")                                                      \
        for (int nf = 0; nf < 4; nf++) {                                       \
            const uint32_t* bp = (const uint32_t*)(bsm                         \
                + (wn + nf * 8 + g) * SB_STRIDE + ks * 8 + tg);                \
            b[nf][0] = bp[0];                                                  \
            b[nf][1] = bp[4];                                                  \
        }                                                                      \
        _Pragma("unroll")                                                      \
        for (int mf = 0; mf < 4; mf++)                                         \
            _Pragma("unroll")                                                  \
            for (int nf = 0; nf < 4; nf++)                                     \
                MMA_TF32(c[mf][nf], a[mf], b[nf]);                             \
    }                                                                          \
} while (0)

    const int nkt = K / BK;    /* 24 */
    LOAD_TILE(0, 0); CP_COMMIT();
    LOAD_TILE(1, 1); CP_COMMIT();

    for (int kt = 0; kt < nkt; kt++) {
        const int st = kt % 3;
        if (kt + 1 < nkt) CP_WAIT1(); else CP_WAIT0();
        __syncthreads();
        COMPUTE(st);
        if (kt + 2 < nkt) {
            LOAD_TILE(kt + 2, (kt + 2) % 3);
            CP_COMMIT();
        }
    }

    /* epilogue */
#pragma unroll
    for (int mf = 0; mf < 4; mf++) {
#pragma unroll
        for (int nf = 0; nf < 4; nf++) {
            const int r0 = m0 + wm + mf * 16 + g;
            const int c0 = n0 + wn + nf * 8 + 2 * tg;
            const float b0 = bias[c0], b1 = bias[c0 + 1];
            float v00 = c[mf][nf][0] + b0, v01 = c[mf][nf][1] + b1;
            float v10 = c[mf][nf][2] + b0, v11 = c[mf][nf][3] + b1;
            if (EPI == 0) {
                const int which = c0 / DIMC;
                const int rem = c0 - which * DIMC;
                const int h = rem >> 6, d = rem & 63;
                float* pf = (which == 0) ? g_qf : (which == 1) ? g_kf : g_vf;
#pragma unroll
                for (int rr = 0; rr < 2; rr++) {
                    int m = r0 + rr * 8;
                    int bidx = m / NN, n = m - bidx * NN;
                    float vx = rr ? v10 : v00, vy = rr ? v11 : v01;
                    size_t off = (((size_t)(bidx * NH + h)) * NN + n) * HD + d;
                    *(float2*)&pf[off] = make_float2(to_tf32(vx), to_tf32(vy));
                }
            } else {
                *(float2*)&Cout[(size_t)r0 * N + c0] = make_float2(v00, v01);
                *(float2*)&Cout[(size_t)(r0 + 8) * N + c0] = make_float2(v10, v11);
            }
        }
    }
#undef LOAD_TILE
#undef COMPUTE
}

/* ------------------------------------------------------------------ */
/* Attention v4: QK^T and PV both in tf32.                             */
/* CTA = 128 thr / 4 warps, 64 q-rows, 16 per warp.                    */
/* S acc-layout -> tf32 A-frag layout via in-register shuffle, then    */
/* exp/relu^2 computed on the permuted values (shuffle once, 2 uses).  */
/* V in smem f32, stride 72 floats -> bank = 8*tg+g, conflict-free.    */
/* ------------------------------------------------------------------ */
#define AS_KV 16384
#define KVSTAGE 35840                     /* K 17408 + V 18432 */
#define ASM_TOTAL (AS_KV + 2 * KVSTAGE)   /* 88064 */
#define KSTRIDE 68                        /* K floats/row; 272 B */
#define VSTRIDE 72                        /* V floats/row; 288 B */

__device__ __forceinline__ void load_kv_tile(
    uint32_t stb, const float* kf, const float* vf, int kt, int tid)
{
#pragma unroll
    for (int i = 0; i < 8; i++) {         /* K: 64 rows x 16 chunks */
        int idx = tid + i * 128;
        int row = idx >> 4, ch = idx & 15;
        CP_ASYNC16(stb + row * 272 + ch * 16,
                   kf + (size_t)(kt * 64 + row) * 64 + ch * 4);
    }
#pragma unroll
    for (int i = 0; i < 8; i++) {         /* V: 64 rows x 16 chunks */
        int idx = tid + i * 128;
        int row = idx >> 4, ch = idx & 15;
        CP_ASYNC16(stb + 17408 + row * 288 + ch * 16,
                   vf + (size_t)(kt * 64 + row) * 64 + ch * 4);
    }
}

__global__ void __launch_bounds__(128) attn4(const float* __restrict__ wblend)
{
    extern __shared__ char sm[];
    const uint32_t sb = smem_u32(sm);
    const int tid = threadIdx.x, warp = tid >> 5, lane = tid & 31;
    const int g = lane >> 2, tg = lane & 3;
    const int qt = blockIdx.x, h = blockIdx.y, b = blockIdx.z;

    const size_t pbase = ((size_t)(b * NH + h)) * NN * HD;
    const float* qfp = g_qf + pbase + (size_t)qt * 64 * HD;
    const float* kfp = g_kf + pbase;
    const float* vfp = g_vf + pbase;

    /* Q: 64 rows x 16 chunks -> two swizzled 8KB halves */
#pragma unroll
    for (int i = 0; i < 8; i++) {
        int idx = tid + i * 128;
        int row = idx >> 4, ch = idx & 15;
        int hh = ch >> 3, c2 = ch & 7;
        CP_ASYNC16(sb + hh * 8192 + row * 128 + ((c2 ^ (row & 7)) * 16),
                   qfp + (size_t)row * 64 + ch * 4);
    }
    load_kv_tile(sb + AS_KV, kfp, vfp, 0, tid);
    CP_COMMIT();

    float accE[8][4], accR[8][4];
#pragma unroll
    for (int n = 0; n < 8; n++)
#pragma unroll
        for (int r = 0; r < 4; r++) { accE[n][r] = 0.f; accR[n][r] = 0.f; }
    float ls0 = 0.f, ls1 = 0.f;
    const float w0 = wblend[0], w1 = wblend[1];

    const int qrow = warp * 16 + (lane & 15);
    const int qh16 = lane >> 4;
    const int src1 = (lane & 28) | (tg >> 1);   /* lane holding col tg pair */
    const int src2 = src1 + 2;                  /* lane holding col tg+4 pair */
    const bool odd = (tg & 1);

    for (int kt = 0; kt < NN / 64; kt++) {
        const int st = kt & 1;
        if (kt + 1 < NN / 64) {
            load_kv_tile(sb + AS_KV + (st ^ 1) * KVSTAGE, kfp, vfp, kt + 1, tid);
            CP_COMMIT();
            CP_WAIT1();
        } else {
            CP_WAIT0();
        }
        __syncthreads();

        const float* Ks = (const float*)(sm + AS_KV + st * KVSTAGE);
        const float* Vs = (const float*)(sm + AS_KV + st * KVSTAGE + 17408);

        /* S = QK^T in tf32 */
        float S[8][4];
#pragma unroll
        for (int j = 0; j < 8; j++)
#pragma unroll
            for (int r = 0; r < 4; r++) S[j][r] = 0.f;

#pragma unroll
        for (int ks = 0; ks < 8; ks++) {
            const int hh = ks >> 2, k2 = ks & 3;
            uint32_t a[4];
            uint32_t addr = sb + hh * 8192 + qrow * 128
                          + (((2 * k2 + qh16) ^ (qrow & 7)) * 16);
            LDMATRIX_X4(a[0], a[1], a[2], a[3], addr);
#pragma unroll
            for (int j = 0; j < 8; j++) {
                const uint32_t* bp = (const uint32_t*)(Ks + (j * 8 + g) * KSTRIDE
                                                       + ks * 8 + tg);
                uint32_t bfr[2];
                bfr[0] = bp[0];
                bfr[1] = bp[4];
                MMA_TF32(S[j], a, bfr);
            }
        }

        /* permute S: acc layout (g,2tg),(g,2tg+1),... -> A-frag layout
           (g,tg),(g+8,tg),(g,tg+4),(g+8,tg+4); then exp / relu^2 */
        uint32_t EA[8][4], RA[8][4];
#pragma unroll
        for (int j = 0; j < 8; j++) {
            float v0 = __shfl_sync(0xffffffffu, S[j][0], src1);
            float v1 = __shfl_sync(0xffffffffu, S[j][1], src1);
            float v2 = __shfl_sync(0xffffffffu, S[j][2], src1);
            float v3 = __shfl_sync(0xffffffffu, S[j][3], src1);
            float u0 = __shfl_sync(0xffffffffu, S[j][0], src2);
            float u1 = __shfl_sync(0xffffffffu, S[j][1], src2);
            float u2 = __shfl_sync(0xffffffffu, S[j][2], src2);
            float u3 = __shfl_sync(0xffffffffu, S[j][3], src2);
            float sa0 = (odd ? v1 : v0) * SCALE_F;   /* (g,    tg)   */
            float sa1 = (odd ? v3 : v2) * SCALE_F;   /* (g+8,  tg)   */
            float sa2 = (odd ? u1 : u0) * SCALE_F;   /* (g,    tg+4) */
            float sa3 = (odd ? u3 : u2) * SCALE_F;   /* (g+8,  tg+4) */
            float e0 = __expf(sa0), e1 = __expf(sa1);
            float e2 = __expf(sa2), e3 = __expf(sa3);
            ls0 += e0 + e2;
            ls1 += e1 + e3;
            float r0 = (sa0 > 0.f) ? sa0 * sa0 : 0.f;
            float r1 = (sa1 > 0.f) ? sa1 * sa1 : 0.f;
            float r2 = (sa2 > 0.f) ? sa2 * sa2 : 0.f;
            float r3 = (sa3 > 0.f) ? sa3 * sa3 : 0.f;
            EA[j][0] = __float_as_uint(to_tf32(e0));
            EA[j][1] = __float_as_uint(to_tf32(e1));
            EA[j][2] = __float_as_uint(to_tf32(e2));
            EA[j][3] = __float_as_uint(to_tf32(e3));
            RA[j][0] = __float_as_uint(to_tf32(r0));
            RA[j][1] = __float_as_uint(to_tf32(r1));
            RA[j][2] = __float_as_uint(to_tf32(r2));
            RA[j][3] = __float_as_uint(to_tf32(r3));
        }

        /* PV in tf32: B-frags from V smem, conflict-free LDS */
#pragma unroll
        for (int kc = 0; kc < 8; kc++) {
            const float* vp = Vs + (kc * 8 + tg) * VSTRIDE + g;
#pragma unroll
            for (int n = 0; n < 8; n++) {
                uint32_t bfr[2];
                bfr[0] = __float_as_uint(vp[n * 8]);
                bfr[1] = __float_as_uint(vp[n * 8 + 4 * VSTRIDE]);
                MMA_TF32(accE[n], EA[kc], bfr);
                MMA_TF32(accR[n], RA[kc], bfr);
            }
        }
        __syncthreads();
    }

    ls0 += __shfl_xor_sync(0xffffffffu, ls0, 1);
    ls0 += __shfl_xor_sync(0xffffffffu, ls0, 2);
    ls1 += __shfl_xor_sync(0xffffffffu, ls1, 1);
    ls1 += __shfl_xor_sync(0xffffffffu, ls1, 2);

    const float ws0 = 1.f / (1.f + __expf(w1 - w0));
    const float ws1 = 1.f - ws0;
    const float inv0 = ws0 / ls0;
    const float inv1 = ws0 / ls1;

    const int row0 = b * NN + qt * 64 + warp * 16 + g;
    float* out0 = g_att + (size_t)row0 * DIMC + h * HD;
    float* out1 = out0 + (size_t)8 * DIMC;
#pragma unroll
    for (int n = 0; n < 8; n++) {
        float2 o0, o1;
        o0.x = to_tf32(accE[n][0] * inv0 + accR[n][0] * ws1);
        o0.y = to_tf32(accE[n][1] * inv0 + accR[n][1] * ws1);
        o1.x = to_tf32(accE[n][2] * inv1 + accR[n][2] * ws1);
        o1.y = to_tf32(accE[n][3] * inv1 + accR[n][3] * ws1);
        *(float2*)(out0 + n * 8 + 2 * tg) = o0;
        *(float2*)(out1 + n * 8 + 2 * tg) = o1;
    }
}

/* ------------------------------------------------------------------ */
extern "C" void kernel_launch(void* const* d_in, const int* in_sizes, int n_in,
                              void* d_out, int out_size)
{
    (void)in_sizes; (void)n_in; (void)out_size;
    const float* x      = (const float*)d_in[0];
    const float* qkv_w  = (const float*)d_in[1];
    const float* qkv_b  = (const float*)d_in[2];
    const float* proj_w = (const float*)d_in[3];
    const float* proj_b = (const float*)d_in[4];
    const float* w      = (const float*)d_in[5];
    float* out = (float*)d_out;

    cudaFuncSetAttribute(tgemm<0>, cudaFuncAttributeMaxDynamicSharedMemorySize, GSM_TOTAL);
    cudaFuncSetAttribute(tgemm<1>, cudaFuncAttributeMaxDynamicSharedMemorySize, GSM_TOTAL);
    cudaFuncSetAttribute(attn4, cudaFuncAttributeMaxDynamicSharedMemorySize, ASM_TOTAL);

    round_x<<<MROWS * DIMC / 1024, 256>>>(x);
    transpose_w<<<dim3(QKVN / 32, DIMC / 32), dim3(32, 8)>>>(qkv_w, DIMC, QKVN, 0);
    transpose_w<<<dim3(DIMC / 32, DIMC / 32), dim3(32, 8)>>>(proj_w, DIMC, DIMC, 1);

    dim3 g1(QKVN / BN, MROWS / BM);   /* 18 x 80 */
    tgemm<0><<<g1, 256, GSM_TOTAL>>>(qkv_b, nullptr, QKVN, DIMC);

    dim3 ga(NN / 64, NH, BB);         /* 10 x 12 x 16 */
    attn4<<<ga, 128, ASM_TOTAL>>>(w);

    dim3 g2(DIMC / BN, MROWS / BM);   /* 3 x 80 */
    tgemm<1><<<g2, 256, GSM_TOTAL>>>(proj_b, out, DIMC, DIMC);
}